// round 1
// baseline (speedup 1.0000x reference)
#include <cuda_runtime.h>
#include <math.h>
#include <stdint.h>

#define SS 1024
#define CS 768
#define CZ 128
#define NH 24
#define DD 32
#define NB 2

// ---- scratch (static device globals: allowed, no cudaMalloc) ----
__device__ float g_emb[NB * 3 * CS];                     // shift|scale|gate
__device__ float g_bsn[NB * SS * CS];                    // adaLN-modulated bs
__device__ float g_qkv[3 * NB * NH * SS * DD];           // (t,b,h,s,d)
__device__ float g_bias[(size_t)NB * NH * SS * SS];      // (b,h,i,j)  ~201MB
__device__ float g_att[NB * SS * CS];                    // attention out (b,s,c)

// ============================================================
// 1. adaLN: emb = silu(t) @ w_adaln + b_adaln   (2 x 2304)
// ============================================================
__global__ void adaln_kernel(const float* __restrict__ t,
                             const float* __restrict__ w,
                             const float* __restrict__ bb) {
    int b = blockIdx.y;
    int n = blockIdx.x * 256 + threadIdx.x;   // 0..2303
    __shared__ float st[CS];
    for (int c = threadIdx.x; c < CS; c += 256) {
        float v = t[b * CS + c];
        st[c] = v / (1.f + __expf(-v));
    }
    __syncthreads();
    float acc = bb[n];
#pragma unroll 4
    for (int c = 0; c < CS; c++) acc = fmaf(st[c], w[c * (3 * CS) + n], acc);
    g_emb[b * 3 * CS + n] = acc;
}

// ============================================================
// 2. bs_norm = LN(bs) * (1+scale) + shift   (block per row)
// ============================================================
__global__ void bsnorm_kernel(const float* __restrict__ bs) {
    int row = blockIdx.x;            // b*1024+s
    int b = row >> 10;
    const float* x = bs + (size_t)row * CS;
    int tid = threadIdx.x;
    float v0 = x[tid], v1 = x[tid + 256], v2 = x[tid + 512];

    __shared__ float red1[8], red2[8];
    float s = v0 + v1 + v2;
    for (int o = 16; o; o >>= 1) s += __shfl_xor_sync(~0u, s, o);
    if ((tid & 31) == 0) red1[tid >> 5] = s;
    __syncthreads();
    float tot = 0.f;
#pragma unroll
    for (int i = 0; i < 8; i++) tot += red1[i];
    float mu = tot * (1.f / CS);

    float d0 = v0 - mu, d1 = v1 - mu, d2 = v2 - mu;
    float q = d0 * d0 + d1 * d1 + d2 * d2;
    for (int o = 16; o; o >>= 1) q += __shfl_xor_sync(~0u, q, o);
    if ((tid & 31) == 0) red2[tid >> 5] = q;
    __syncthreads();
    float tot2 = 0.f;
#pragma unroll
    for (int i = 0; i < 8; i++) tot2 += red2[i];
    float rsig = rsqrtf(tot2 * (1.f / CS) + 1e-5f);

    const float* e = g_emb + b * 3 * CS;
    float* outp = g_bsn + (size_t)row * CS;
    outp[tid]       = d0 * rsig * (1.f + e[CS + tid])       + e[tid];
    outp[tid + 256] = d1 * rsig * (1.f + e[CS + tid + 256]) + e[tid + 256];
    outp[tid + 512] = d2 * rsig * (1.f + e[CS + tid + 512]) + e[tid + 512];
}

// ============================================================
// 3. QKV GEMM: g_bsn(2048x768) @ [wq|wk|wv](768x2304)
//    BM=BN=64, BK=16, 256 threads, 4x4 micro-tile
//    epilogue scatters into (t,b,h,s,d)
// ============================================================
__global__ void qkv_gemm(const float* __restrict__ wq,
                         const float* __restrict__ wk,
                         const float* __restrict__ wv) {
    const int n0 = blockIdx.x * 64, m0 = blockIdx.y * 64;
    int sel = n0 / CS;
    const float* W = (sel == 0) ? wq : ((sel == 1) ? wk : wv);
    int nc = n0 - sel * CS;

    __shared__ float As[16][68];
    __shared__ float Bs[16][64];
    int tid = threadIdx.x;
    int tm = tid >> 4, tn = tid & 15;
    float acc[4][4] = {};

    int ar = tid >> 2, ac = (tid & 3) * 4;
    int br = tid >> 4, bc = (tid & 15) * 4;
    const float* Ap = g_bsn + (size_t)(m0 + ar) * CS + ac;
    const float* Bp = W + (size_t)br * CS + nc + bc;

    for (int k0 = 0; k0 < CS; k0 += 16) {
        float4 a4 = *(const float4*)(Ap + k0);
        float4 b4 = *(const float4*)(Bp + (size_t)k0 * CS);
        As[ac + 0][ar] = a4.x; As[ac + 1][ar] = a4.y;
        As[ac + 2][ar] = a4.z; As[ac + 3][ar] = a4.w;
        *(float4*)&Bs[br][bc] = b4;
        __syncthreads();
#pragma unroll
        for (int kk = 0; kk < 16; kk++) {
            float4 av = *(const float4*)&As[kk][tm * 4];
            float4 bv = *(const float4*)&Bs[kk][tn * 4];
            acc[0][0] += av.x * bv.x; acc[0][1] += av.x * bv.y; acc[0][2] += av.x * bv.z; acc[0][3] += av.x * bv.w;
            acc[1][0] += av.y * bv.x; acc[1][1] += av.y * bv.y; acc[1][2] += av.y * bv.z; acc[1][3] += av.y * bv.w;
            acc[2][0] += av.z * bv.x; acc[2][1] += av.z * bv.y; acc[2][2] += av.z * bv.z; acc[2][3] += av.z * bv.w;
            acc[3][0] += av.w * bv.x; acc[3][1] += av.w * bv.y; acc[3][2] += av.w * bv.z; acc[3][3] += av.w * bv.w;
        }
        __syncthreads();
    }
#pragma unroll
    for (int qi = 0; qi < 4; qi++) {
        int m = m0 + tm * 4 + qi;
        int b = m >> 10, srow = m & 1023;
#pragma unroll
        for (int j = 0; j < 4; j++) {
            int n = nc + tn * 4 + j;      // 0..767 within selected weight
            int h = n >> 5, d = n & 31;
            g_qkv[(((size_t)(sel * NB + b) * NH + h) * SS + srow) * DD + d] = acc[qi][j];
        }
    }
}

// ============================================================
// 4. RMS norm q,k (warp per 32-vec, in place)
// ============================================================
__global__ void rms_kernel(const float* __restrict__ wq_r,
                           const float* __restrict__ wk_r) {
    int warp = (blockIdx.x * blockDim.x + threadIdx.x) >> 5;
    int lane = threadIdx.x & 31;
    const int NROWS = 2 * NB * NH * SS;
    if (warp >= NROWS) return;
    const float* w = (warp < NB * NH * SS) ? wq_r : wk_r;
    float* p = g_qkv + (size_t)warp * DD;
    float v = p[lane];
    float ss = v * v;
    for (int o = 16; o; o >>= 1) ss += __shfl_xor_sync(~0u, ss, o);
    p[lane] = v * rsqrtf(ss * (1.f / DD) + 1e-5f) * w[lane];
}

// ============================================================
// 5. bias: LN(z)@w_z folded -> g_bias[b,h,i,j] (+mask,+beta)
//    bias = rsig*(z@W' - mu*A) + B',  W' = ln_w * w_z
// ============================================================
__global__ void bias_kernel(const float* __restrict__ z,
                            const int* __restrict__ zmask,
                            const float* __restrict__ beta,
                            const float* __restrict__ lnw,
                            const float* __restrict__ lnb,
                            const float* __restrict__ wz) {
    __shared__ float Wp[CZ][NH];        // 12KB, 16B-aligned rows (24 floats = 96B)
    __shared__ float Ah[NH], Bh[NH];
    int i = blockIdx.x;
    for (int idx = threadIdx.x; idx < CZ * NH; idx += 256) {
        int c = idx / NH;
        Wp[c][idx - c * NH] = lnw[c] * wz[idx];
    }
    __syncthreads();
    if (threadIdx.x < NH) {
        float a = 0.f, bsum = 0.f;
        for (int c = 0; c < CZ; c++) {
            a += Wp[c][threadIdx.x];
            bsum += lnb[c] * wz[c * NH + threadIdx.x];
        }
        Ah[threadIdx.x] = a; Bh[threadIdx.x] = bsum;
    }
    __syncthreads();

    for (int jj = 0; jj < 4; jj++) {
        int j = threadIdx.x + jj * 256;
        int ij = i * SS + j;
        if (zmask[ij] == 0) {
#pragma unroll
            for (int h = 0; h < NH; h++) {
                g_bias[(size_t)(h * SS + i) * SS + j] = -1e9f;
                g_bias[(size_t)((NH + h) * SS + i) * SS + j] = -1e9f;
            }
            continue;
        }
        float b0 = beta[ij], b1 = beta[SS * SS + ij];
        const float4* zp = (const float4*)(z + (size_t)ij * CZ);
        float acc[NH];
#pragma unroll
        for (int h = 0; h < NH; h++) acc[h] = 0.f;
        float sum = 0.f, sq = 0.f;
        for (int c4 = 0; c4 < CZ / 4; c4++) {
            float4 v = zp[c4];
            sum += v.x + v.y + v.z + v.w;
            sq += v.x * v.x + v.y * v.y + v.z * v.z + v.w * v.w;
            int c = c4 * 4;
            float vv[4] = {v.x, v.y, v.z, v.w};
#pragma unroll
            for (int u = 0; u < 4; u++) {
                const float4* wrow = (const float4*)&Wp[c + u][0];
                float vc = vv[u];
                float4 w0 = wrow[0], w1 = wrow[1], w2 = wrow[2];
                float4 w3 = wrow[3], w4 = wrow[4], w5 = wrow[5];
                acc[0]  += vc * w0.x; acc[1]  += vc * w0.y; acc[2]  += vc * w0.z; acc[3]  += vc * w0.w;
                acc[4]  += vc * w1.x; acc[5]  += vc * w1.y; acc[6]  += vc * w1.z; acc[7]  += vc * w1.w;
                acc[8]  += vc * w2.x; acc[9]  += vc * w2.y; acc[10] += vc * w2.z; acc[11] += vc * w2.w;
                acc[12] += vc * w3.x; acc[13] += vc * w3.y; acc[14] += vc * w3.z; acc[15] += vc * w3.w;
                acc[16] += vc * w4.x; acc[17] += vc * w4.y; acc[18] += vc * w4.z; acc[19] += vc * w4.w;
                acc[20] += vc * w5.x; acc[21] += vc * w5.y; acc[22] += vc * w5.z; acc[23] += vc * w5.w;
            }
        }
        float mu = sum * (1.f / CZ);
        float var = sq * (1.f / CZ) - mu * mu;
        float rsig = rsqrtf(var + 1e-5f);
#pragma unroll
        for (int h = 0; h < NH; h++) {
            float hb = rsig * (acc[h] - mu * Ah[h]) + Bh[h];
            g_bias[(size_t)(h * SS + i) * SS + j] = hb + b0;
            g_bias[(size_t)((NH + h) * SS + i) * SS + j] = hb + b1;
        }
    }
}

// ============================================================
// 6. flash attention with precomputed bias
//    block = (qtile=64, h, b); 256 threads; BK=64
// ============================================================
__global__ void attn_kernel() {
    __shared__ float q_sT[DD][68];
    __shared__ float k_sT[DD][68];
    __shared__ float v_s[64][DD];
    __shared__ float p_sT[64][68];

    int b = blockIdx.z, h = blockIdx.y, q0 = blockIdx.x * 64;
    int tid = threadIdx.x;
    int tq = tid >> 4, tn = tid & 15;

    const float* qptr = g_qkv + ((size_t)(0 * NB + b) * NH + h) * SS * DD;
    const float* kptr = g_qkv + ((size_t)(1 * NB + b) * NH + h) * SS * DD;
    const float* vptr = g_qkv + ((size_t)(2 * NB + b) * NH + h) * SS * DD;
    const float* biasp = g_bias + ((size_t)(b * NH + h) * SS + q0) * SS;

    // load q tile transposed, scaled by 1/sqrt(D)
    for (int idx = tid; idx < 512; idx += 256) {
        int r = idx >> 3, f = idx & 7;
        float4 v = *(const float4*)(qptr + (size_t)(q0 + r) * DD + f * 4);
        const float sc = 0.17677669529663687f;
        q_sT[f * 4 + 0][r] = v.x * sc; q_sT[f * 4 + 1][r] = v.y * sc;
        q_sT[f * 4 + 2][r] = v.z * sc; q_sT[f * 4 + 3][r] = v.w * sc;
    }
    float m_run[4], l_run[4], o[4][2];
#pragma unroll
    for (int qi = 0; qi < 4; qi++) {
        m_run[qi] = -INFINITY; l_run[qi] = 0.f; o[qi][0] = 0.f; o[qi][1] = 0.f;
    }
    __syncthreads();

    for (int kt = 0; kt < 16; kt++) {
        int k0 = kt * 64;
        for (int idx = tid; idx < 512; idx += 256) {
            int r = idx >> 3, f = idx & 7;
            float4 kv = *(const float4*)(kptr + (size_t)(k0 + r) * DD + f * 4);
            k_sT[f * 4 + 0][r] = kv.x; k_sT[f * 4 + 1][r] = kv.y;
            k_sT[f * 4 + 2][r] = kv.z; k_sT[f * 4 + 3][r] = kv.w;
            float4 vv = *(const float4*)(vptr + (size_t)(k0 + r) * DD + f * 4);
            *(float4*)&v_s[r][f * 4] = vv;
        }
        __syncthreads();

        float s[4][4] = {};
#pragma unroll
        for (int d = 0; d < DD; d++) {
            float4 av = *(const float4*)&q_sT[d][tq * 4];
            float4 bv = *(const float4*)&k_sT[d][tn * 4];
            s[0][0] += av.x * bv.x; s[0][1] += av.x * bv.y; s[0][2] += av.x * bv.z; s[0][3] += av.x * bv.w;
            s[1][0] += av.y * bv.x; s[1][1] += av.y * bv.y; s[1][2] += av.y * bv.z; s[1][3] += av.y * bv.w;
            s[2][0] += av.z * bv.x; s[2][1] += av.z * bv.y; s[2][2] += av.z * bv.z; s[2][3] += av.z * bv.w;
            s[3][0] += av.w * bv.x; s[3][1] += av.w * bv.y; s[3][2] += av.w * bv.z; s[3][3] += av.w * bv.w;
        }
#pragma unroll
        for (int qi = 0; qi < 4; qi++) {
            float4 bv = *(const float4*)(biasp + (size_t)(tq * 4 + qi) * SS + k0 + tn * 4);
            s[qi][0] += bv.x; s[qi][1] += bv.y; s[qi][2] += bv.z; s[qi][3] += bv.w;
        }
#pragma unroll
        for (int qi = 0; qi < 4; qi++) {
            float mx = fmaxf(fmaxf(s[qi][0], s[qi][1]), fmaxf(s[qi][2], s[qi][3]));
            for (int off = 8; off; off >>= 1) mx = fmaxf(mx, __shfl_xor_sync(~0u, mx, off));
            float mnew = fmaxf(m_run[qi], mx);
            float alpha = __expf(m_run[qi] - mnew);
            float rs = 0.f;
#pragma unroll
            for (int kj = 0; kj < 4; kj++) { s[qi][kj] = __expf(s[qi][kj] - mnew); rs += s[qi][kj]; }
            for (int off = 8; off; off >>= 1) rs += __shfl_xor_sync(~0u, rs, off);
            l_run[qi] = l_run[qi] * alpha + rs;
            m_run[qi] = mnew;
            o[qi][0] *= alpha; o[qi][1] *= alpha;
        }
#pragma unroll
        for (int kj = 0; kj < 4; kj++) {
            float4 pv = make_float4(s[0][kj], s[1][kj], s[2][kj], s[3][kj]);
            *(float4*)&p_sT[tn * 4 + kj][tq * 4] = pv;
        }
        __syncthreads();
#pragma unroll
        for (int kk = 0; kk < 64; kk++) {
            float4 p4 = *(const float4*)&p_sT[kk][tq * 4];
            float2 v2 = *(const float2*)&v_s[kk][tn * 2];
            o[0][0] += p4.x * v2.x; o[0][1] += p4.x * v2.y;
            o[1][0] += p4.y * v2.x; o[1][1] += p4.y * v2.y;
            o[2][0] += p4.z * v2.x; o[2][1] += p4.z * v2.y;
            o[3][0] += p4.w * v2.x; o[3][1] += p4.w * v2.y;
        }
        __syncthreads();
    }
#pragma unroll
    for (int qi = 0; qi < 4; qi++) {
        float inv = 1.f / l_run[qi];
        int srow = q0 + tq * 4 + qi;
        float* op = g_att + ((size_t)(b * SS + srow)) * CS + h * DD + tn * 2;
        op[0] = o[qi][0] * inv;
        op[1] = o[qi][1] * inv;
    }
}

// ============================================================
// 7. out proj: (g_att @ w_o + b_o) * gate  -> d_out
// ============================================================
__global__ void proj_gemm(const float* __restrict__ W,
                          const float* __restrict__ b_o,
                          float* __restrict__ out) {
    const int n0 = blockIdx.x * 64, m0 = blockIdx.y * 64;
    __shared__ float As[16][68];
    __shared__ float Bs[16][64];
    int tid = threadIdx.x;
    int tm = tid >> 4, tn = tid & 15;
    float acc[4][4] = {};

    int ar = tid >> 2, ac = (tid & 3) * 4;
    int br = tid >> 4, bc = (tid & 15) * 4;
    const float* Ap = g_att + (size_t)(m0 + ar) * CS + ac;
    const float* Bp = W + (size_t)br * CS + n0 + bc;

    for (int k0 = 0; k0 < CS; k0 += 16) {
        float4 a4 = *(const float4*)(Ap + k0);
        float4 b4 = *(const float4*)(Bp + (size_t)k0 * CS);
        As[ac + 0][ar] = a4.x; As[ac + 1][ar] = a4.y;
        As[ac + 2][ar] = a4.z; As[ac + 3][ar] = a4.w;
        *(float4*)&Bs[br][bc] = b4;
        __syncthreads();
#pragma unroll
        for (int kk = 0; kk < 16; kk++) {
            float4 av = *(const float4*)&As[kk][tm * 4];
            float4 bv = *(const float4*)&Bs[kk][tn * 4];
            acc[0][0] += av.x * bv.x; acc[0][1] += av.x * bv.y; acc[0][2] += av.x * bv.z; acc[0][3] += av.x * bv.w;
            acc[1][0] += av.y * bv.x; acc[1][1] += av.y * bv.y; acc[1][2] += av.y * bv.z; acc[1][3] += av.y * bv.w;
            acc[2][0] += av.z * bv.x; acc[2][1] += av.z * bv.y; acc[2][2] += av.z * bv.z; acc[2][3] += av.z * bv.w;
            acc[3][0] += av.w * bv.x; acc[3][1] += av.w * bv.y; acc[3][2] += av.w * bv.z; acc[3][3] += av.w * bv.w;
        }
        __syncthreads();
    }
#pragma unroll
    for (int qi = 0; qi < 4; qi++) {
        int m = m0 + tm * 4 + qi;
        int b = m >> 10;
        const float* gate = g_emb + b * 3 * CS + 2 * CS;
#pragma unroll
        for (int j = 0; j < 4; j++) {
            int n = n0 + tn * 4 + j;
            out[(size_t)m * CS + n] = (acc[qi][j] + b_o[n]) * gate[n];
        }
    }
}

// ============================================================
extern "C" void kernel_launch(void* const* d_in, const int* in_sizes, int n_in,
                              void* d_out, int out_size) {
    const float* bs      = (const float*)d_in[0];
    const float* z       = (const float*)d_in[1];
    const float* t       = (const float*)d_in[2];
    const float* beta    = (const float*)d_in[3];
    const int*   z_mask  = (const int*)  d_in[4];
    const float* w_adaln = (const float*)d_in[5];
    const float* b_adaln = (const float*)d_in[6];
    const float* ln_z_w  = (const float*)d_in[7];
    const float* ln_z_b  = (const float*)d_in[8];
    const float* w_q     = (const float*)d_in[9];
    const float* w_k     = (const float*)d_in[10];
    const float* w_v     = (const float*)d_in[11];
    const float* w_z     = (const float*)d_in[12];
    const float* rms_q_w = (const float*)d_in[13];
    const float* rms_k_w = (const float*)d_in[14];
    const float* w_o     = (const float*)d_in[15];
    const float* b_o     = (const float*)d_in[16];
    float* out = (float*)d_out;

    adaln_kernel<<<dim3(9, 2), 256>>>(t, w_adaln, b_adaln);
    bsnorm_kernel<<<NB * SS, 256>>>(bs);
    qkv_gemm<<<dim3(36, 32), 256>>>(w_q, w_k, w_v);
    rms_kernel<<<12288, 256>>>(rms_q_w, rms_k_w);
    bias_kernel<<<SS, 256>>>(z, z_mask, beta, ln_z_w, ln_z_b, w_z);
    attn_kernel<<<dim3(16, NH, NB), 256>>>();
    proj_gemm<<<dim3(12, 32), 256>>>(w_o, b_o, out);
}

// round 2
// speedup vs baseline: 1.2567x; 1.2567x over previous
#include <cuda_runtime.h>
#include <math.h>
#include <stdint.h>

#define SS 1024
#define CS 768
#define CZ 128
#define NH 24
#define DD 32
#define NB 2

// ---- scratch ----
__device__ float g_emb[NB * 3 * CS];
__device__ float g_bsn[NB * SS * CS];
__device__ float g_qkv[3 * NB * NH * SS * DD];
__device__ float g_bias[(size_t)NB * NH * SS * SS];
__device__ float g_att[NB * SS * CS];

__device__ __forceinline__ unsigned f2tf(float x) {
    unsigned u; asm("cvt.rna.tf32.f32 %0, %1;" : "=r"(u) : "f"(x)); return u;
}
__device__ __forceinline__ void mma8(float* c, const unsigned* a, unsigned b0, unsigned b1) {
    asm volatile("mma.sync.aligned.m16n8k8.row.col.f32.tf32.tf32.f32 "
        "{%0,%1,%2,%3},{%4,%5,%6,%7},{%8,%9},{%0,%1,%2,%3};"
        : "+f"(c[0]), "+f"(c[1]), "+f"(c[2]), "+f"(c[3])
        : "r"(a[0]), "r"(a[1]), "r"(a[2]), "r"(a[3]), "r"(b0), "r"(b1));
}

// ============================================================
// 1. adaLN
// ============================================================
__global__ void adaln_kernel(const float* __restrict__ t,
                             const float* __restrict__ w,
                             const float* __restrict__ bb) {
    int b = blockIdx.y;
    int n = blockIdx.x * 256 + threadIdx.x;
    __shared__ float st[CS];
    for (int c = threadIdx.x; c < CS; c += 256) {
        float v = t[b * CS + c];
        st[c] = v / (1.f + __expf(-v));
    }
    __syncthreads();
    float acc = bb[n];
#pragma unroll 4
    for (int c = 0; c < CS; c++) acc = fmaf(st[c], w[c * (3 * CS) + n], acc);
    g_emb[b * 3 * CS + n] = acc;
}

// ============================================================
// 2. bs LayerNorm + adaLN modulate
// ============================================================
__global__ void bsnorm_kernel(const float* __restrict__ bs) {
    int row = blockIdx.x;
    int b = row >> 10;
    const float* x = bs + (size_t)row * CS;
    int tid = threadIdx.x;
    float v0 = x[tid], v1 = x[tid + 256], v2 = x[tid + 512];

    __shared__ float red1[8], red2[8];
    float s = v0 + v1 + v2;
    for (int o = 16; o; o >>= 1) s += __shfl_xor_sync(~0u, s, o);
    if ((tid & 31) == 0) red1[tid >> 5] = s;
    __syncthreads();
    float tot = 0.f;
#pragma unroll
    for (int i = 0; i < 8; i++) tot += red1[i];
    float mu = tot * (1.f / CS);

    float d0 = v0 - mu, d1 = v1 - mu, d2 = v2 - mu;
    float q = d0 * d0 + d1 * d1 + d2 * d2;
    for (int o = 16; o; o >>= 1) q += __shfl_xor_sync(~0u, q, o);
    if ((tid & 31) == 0) red2[tid >> 5] = q;
    __syncthreads();
    float tot2 = 0.f;
#pragma unroll
    for (int i = 0; i < 8; i++) tot2 += red2[i];
    float rsig = rsqrtf(tot2 * (1.f / CS) + 1e-5f);

    const float* e = g_emb + b * 3 * CS;
    float* outp = g_bsn + (size_t)row * CS;
    outp[tid]       = d0 * rsig * (1.f + e[CS + tid])       + e[tid];
    outp[tid + 256] = d1 * rsig * (1.f + e[CS + tid + 256]) + e[tid + 256];
    outp[tid + 512] = d2 * rsig * (1.f + e[CS + tid + 512]) + e[tid + 512];
}

// ============================================================
// 3. QKV GEMM via tf32 mma: 2048x768 @ 768x(3*768)
//    BM=BN=64, BK=32, 128 threads (4 warps, warp = m16 x n64)
// ============================================================
__global__ __launch_bounds__(128) void qkv_mma(const float* __restrict__ wq,
                                               const float* __restrict__ wk,
                                               const float* __restrict__ wv) {
    __shared__ unsigned As[64][40];   // [m][k] pad 40: frag loads conflict-free
    __shared__ unsigned Bs[32][72];   // [k][n] pad 72: frag loads conflict-free
    int bx = blockIdx.x;
    int sel = bx / 12, n0 = (bx % 12) * 64, m0 = blockIdx.y * 64;
    const float* W = (sel == 0) ? wq : ((sel == 1) ? wk : wv);
    int tid = threadIdx.x, w = tid >> 5, lane = tid & 31, g = lane >> 2, c = lane & 3;
    float acc[8][4] = {};

    for (int k0 = 0; k0 < CS; k0 += 32) {
        __syncthreads();
        for (int i = tid; i < 512; i += 128) {
            int r = i >> 3, c4 = (i & 7) * 4;
            float4 v = *(const float4*)(g_bsn + (size_t)(m0 + r) * CS + k0 + c4);
            uint4 u = {f2tf(v.x), f2tf(v.y), f2tf(v.z), f2tf(v.w)};
            *(uint4*)&As[r][c4] = u;
        }
        for (int i = tid; i < 512; i += 128) {
            int r = i >> 4, c4 = (i & 15) * 4;
            float4 v = *(const float4*)(W + (size_t)(k0 + r) * CS + n0 + c4);
            uint4 u = {f2tf(v.x), f2tf(v.y), f2tf(v.z), f2tf(v.w)};
            *(uint4*)&Bs[r][c4] = u;
        }
        __syncthreads();
#pragma unroll
        for (int ks = 0; ks < 4; ks++) {
            unsigned a[4] = {As[16 * w + g][8 * ks + c], As[16 * w + g + 8][8 * ks + c],
                             As[16 * w + g][8 * ks + c + 4], As[16 * w + g + 8][8 * ks + c + 4]};
#pragma unroll
            for (int nt = 0; nt < 8; nt++)
                mma8(acc[nt], a, Bs[8 * ks + c][8 * nt + g], Bs[8 * ks + c + 4][8 * nt + g]);
        }
    }
    int r0 = m0 + 16 * w + g;
    int b = r0 >> 10, s0 = r0 & 1023, s1 = s0 + 8;
#pragma unroll
    for (int nt = 0; nt < 8; nt++) {
        int col = n0 + 8 * nt + 2 * c;      // 0..767 within selected weight
        int h = col >> 5, d = col & 31;     // pair (d, d+1) stays in one head
        float* p0 = g_qkv + (((size_t)(sel * NB + b) * NH + h) * SS + s0) * DD + d;
        float* p1 = g_qkv + (((size_t)(sel * NB + b) * NH + h) * SS + s1) * DD + d;
        p0[0] = acc[nt][0]; p0[1] = acc[nt][1];
        p1[0] = acc[nt][2]; p1[1] = acc[nt][3];
    }
}

// ============================================================
// 4. RMS norm q,k (warp per 32-vec, in place)
// ============================================================
__global__ void rms_kernel(const float* __restrict__ wq_r,
                           const float* __restrict__ wk_r) {
    int warp = (blockIdx.x * blockDim.x + threadIdx.x) >> 5;
    int lane = threadIdx.x & 31;
    const int NROWS = 2 * NB * NH * SS;
    if (warp >= NROWS) return;
    const float* w = (warp < NB * NH * SS) ? wq_r : wk_r;
    float* p = g_qkv + (size_t)warp * DD;
    float v = p[lane];
    float ss = v * v;
    for (int o = 16; o; o >>= 1) ss += __shfl_xor_sync(~0u, ss, o);
    p[lane] = v * rsqrtf(ss * (1.f / DD) + 1e-5f) * w[lane];
}

// ============================================================
// 5. bias: LN(z)@w_z folded + mask + beta -> g_bias[b,h,i,j]
// ============================================================
__global__ void bias_kernel(const float* __restrict__ z,
                            const int* __restrict__ zmask,
                            const float* __restrict__ beta,
                            const float* __restrict__ lnw,
                            const float* __restrict__ lnb,
                            const float* __restrict__ wz) {
    __shared__ float Wp[CZ][NH];
    __shared__ float Ah[NH], Bh[NH];
    int i = blockIdx.x;
    for (int idx = threadIdx.x; idx < CZ * NH; idx += 256) {
        int cc = idx / NH;
        Wp[cc][idx - cc * NH] = lnw[cc] * wz[idx];
    }
    __syncthreads();
    if (threadIdx.x < NH) {
        float a = 0.f, bsum = 0.f;
        for (int cc = 0; cc < CZ; cc++) {
            a += Wp[cc][threadIdx.x];
            bsum += lnb[cc] * wz[cc * NH + threadIdx.x];
        }
        Ah[threadIdx.x] = a; Bh[threadIdx.x] = bsum;
    }
    __syncthreads();

    for (int jj = 0; jj < 4; jj++) {
        int j = threadIdx.x + jj * 256;
        int ij = i * SS + j;
        if (zmask[ij] == 0) {
#pragma unroll
            for (int h = 0; h < NH; h++) {
                g_bias[(size_t)(h * SS + i) * SS + j] = -1e9f;
                g_bias[(size_t)((NH + h) * SS + i) * SS + j] = -1e9f;
            }
            continue;
        }
        float b0 = beta[ij], b1 = beta[SS * SS + ij];
        const float4* zp = (const float4*)(z + (size_t)ij * CZ);
        float acc[NH];
#pragma unroll
        for (int h = 0; h < NH; h++) acc[h] = 0.f;
        float sum = 0.f, sq = 0.f;
        for (int c4 = 0; c4 < CZ / 4; c4++) {
            float4 v = zp[c4];
            sum += v.x + v.y + v.z + v.w;
            sq += v.x * v.x + v.y * v.y + v.z * v.z + v.w * v.w;
            int cc = c4 * 4;
            float vv[4] = {v.x, v.y, v.z, v.w};
#pragma unroll
            for (int u = 0; u < 4; u++) {
                const float4* wrow = (const float4*)&Wp[cc + u][0];
                float vc = vv[u];
                float4 w0 = wrow[0], w1 = wrow[1], w2 = wrow[2];
                float4 w3 = wrow[3], w4 = wrow[4], w5 = wrow[5];
                acc[0]  += vc * w0.x; acc[1]  += vc * w0.y; acc[2]  += vc * w0.z; acc[3]  += vc * w0.w;
                acc[4]  += vc * w1.x; acc[5]  += vc * w1.y; acc[6]  += vc * w1.z; acc[7]  += vc * w1.w;
                acc[8]  += vc * w2.x; acc[9]  += vc * w2.y; acc[10] += vc * w2.z; acc[11] += vc * w2.w;
                acc[12] += vc * w3.x; acc[13] += vc * w3.y; acc[14] += vc * w3.z; acc[15] += vc * w3.w;
                acc[16] += vc * w4.x; acc[17] += vc * w4.y; acc[18] += vc * w4.z; acc[19] += vc * w4.w;
                acc[20] += vc * w5.x; acc[21] += vc * w5.y; acc[22] += vc * w5.z; acc[23] += vc * w5.w;
            }
        }
        float mu = sum * (1.f / CZ);
        float var = sq * (1.f / CZ) - mu * mu;
        float rsig = rsqrtf(var + 1e-5f);
#pragma unroll
        for (int h = 0; h < NH; h++) {
            float hb = rsig * (acc[h] - mu * Ah[h]) + Bh[h];
            g_bias[(size_t)(h * SS + i) * SS + j] = hb + b0;
            g_bias[(size_t)((NH + h) * SS + i) * SS + j] = hb + b1;
        }
    }
}

// ============================================================
// 6. flash attention via tf32 mma
//    block = (qtile=64, h, b); 128 threads (4 warps, warp = 16 q-rows)
// ============================================================
__global__ __launch_bounds__(128) void attn_mma() {
    __shared__ unsigned Qs[64][40];
    __shared__ unsigned Ks[64][40];
    __shared__ unsigned Vs[64][40];
    __shared__ unsigned Ps[64][68];   // bias staging (float bits) then P (tf32 bits)

    int b = blockIdx.z, h = blockIdx.y, q0 = blockIdx.x * 64;
    int tid = threadIdx.x, w = tid >> 5, lane = tid & 31, g = lane >> 2, c = lane & 3;

    const float* qptr = g_qkv + ((size_t)(0 * NB + b) * NH + h) * SS * DD;
    const float* kptr = g_qkv + ((size_t)(1 * NB + b) * NH + h) * SS * DD;
    const float* vptr = g_qkv + ((size_t)(2 * NB + b) * NH + h) * SS * DD;
    const float* biasp = g_bias + ((size_t)(b * NH + h) * SS + q0) * SS;
    const float sc = 0.17677669529663687f;

    for (int i = tid; i < 512; i += 128) {
        int r = i >> 3, c4 = (i & 7) * 4;
        float4 v = *(const float4*)(qptr + (size_t)(q0 + r) * DD + c4);
        uint4 u = {f2tf(v.x * sc), f2tf(v.y * sc), f2tf(v.z * sc), f2tf(v.w * sc)};
        *(uint4*)&Qs[r][c4] = u;
    }
    __syncthreads();
    unsigned qa[4][4];
#pragma unroll
    for (int ks = 0; ks < 4; ks++) {
        qa[ks][0] = Qs[16 * w + g][8 * ks + c];
        qa[ks][1] = Qs[16 * w + g + 8][8 * ks + c];
        qa[ks][2] = Qs[16 * w + g][8 * ks + c + 4];
        qa[ks][3] = Qs[16 * w + g + 8][8 * ks + c + 4];
    }
    float mr0 = -1e30f, mr1 = -1e30f, l0 = 0.f, l1 = 0.f;
    float o[4][4] = {};

    for (int kt = 0; kt < 16; kt++) {
        int k0 = kt * 64;
        __syncthreads();
        for (int i = tid; i < 512; i += 128) {
            int r = i >> 3, c4 = (i & 7) * 4;
            float4 kv = *(const float4*)(kptr + (size_t)(k0 + r) * DD + c4);
            uint4 u = {f2tf(kv.x), f2tf(kv.y), f2tf(kv.z), f2tf(kv.w)};
            *(uint4*)&Ks[r][c4] = u;
            float4 vv = *(const float4*)(vptr + (size_t)(k0 + r) * DD + c4);
            uint4 u2 = {f2tf(vv.x), f2tf(vv.y), f2tf(vv.z), f2tf(vv.w)};
            *(uint4*)&Vs[r][c4] = u2;
        }
        for (int i = tid; i < 1024; i += 128) {
            int r = i >> 4, c4 = (i & 15) * 4;
            *(float4*)&Ps[r][c4] = *(const float4*)(biasp + (size_t)r * SS + k0 + c4);
        }
        __syncthreads();

        float s[8][4] = {};
#pragma unroll
        for (int ks = 0; ks < 4; ks++) {
#pragma unroll
            for (int nt = 0; nt < 8; nt++)
                mma8(s[nt], qa[ks], Ks[8 * nt + g][8 * ks + c], Ks[8 * nt + g][8 * ks + c + 4]);
        }
        // bias add + row max (bias fully consumed before P overwrites Ps)
        float mx0 = -1e30f, mx1 = -1e30f;
#pragma unroll
        for (int nt = 0; nt < 8; nt++) {
            s[nt][0] += __uint_as_float(Ps[16 * w + g][8 * nt + 2 * c]);
            s[nt][1] += __uint_as_float(Ps[16 * w + g][8 * nt + 2 * c + 1]);
            s[nt][2] += __uint_as_float(Ps[16 * w + g + 8][8 * nt + 2 * c]);
            s[nt][3] += __uint_as_float(Ps[16 * w + g + 8][8 * nt + 2 * c + 1]);
            mx0 = fmaxf(mx0, fmaxf(s[nt][0], s[nt][1]));
            mx1 = fmaxf(mx1, fmaxf(s[nt][2], s[nt][3]));
        }
        mx0 = fmaxf(mx0, __shfl_xor_sync(~0u, mx0, 1));
        mx0 = fmaxf(mx0, __shfl_xor_sync(~0u, mx0, 2));
        mx1 = fmaxf(mx1, __shfl_xor_sync(~0u, mx1, 1));
        mx1 = fmaxf(mx1, __shfl_xor_sync(~0u, mx1, 2));
        float mn0 = fmaxf(mr0, mx0), mn1 = fmaxf(mr1, mx1);
        float a0 = __expf(mr0 - mn0), a1 = __expf(mr1 - mn1);
        float rs0 = 0.f, rs1 = 0.f;
#pragma unroll
        for (int nt = 0; nt < 8; nt++) {
            float e0 = __expf(s[nt][0] - mn0), e1 = __expf(s[nt][1] - mn0);
            float e2 = __expf(s[nt][2] - mn1), e3 = __expf(s[nt][3] - mn1);
            rs0 += e0 + e1; rs1 += e2 + e3;
            uint2 u0 = {f2tf(e0), f2tf(e1)};
            *(uint2*)&Ps[16 * w + g][8 * nt + 2 * c] = u0;
            uint2 u1 = {f2tf(e2), f2tf(e3)};
            *(uint2*)&Ps[16 * w + g + 8][8 * nt + 2 * c] = u1;
        }
        rs0 += __shfl_xor_sync(~0u, rs0, 1); rs0 += __shfl_xor_sync(~0u, rs0, 2);
        rs1 += __shfl_xor_sync(~0u, rs1, 1); rs1 += __shfl_xor_sync(~0u, rs1, 2);
        l0 = l0 * a0 + rs0; l1 = l1 * a1 + rs1;
        mr0 = mn0; mr1 = mn1;
#pragma unroll
        for (int nt = 0; nt < 4; nt++) {
            o[nt][0] *= a0; o[nt][1] *= a0; o[nt][2] *= a1; o[nt][3] *= a1;
        }
        __syncwarp();   // P rows for this warp written by this warp only
#pragma unroll
        for (int ks = 0; ks < 8; ks++) {
            unsigned pa[4] = {Ps[16 * w + g][8 * ks + c], Ps[16 * w + g + 8][8 * ks + c],
                              Ps[16 * w + g][8 * ks + c + 4], Ps[16 * w + g + 8][8 * ks + c + 4]};
#pragma unroll
            for (int nt = 0; nt < 4; nt++)
                mma8(o[nt], pa, Vs[8 * ks + c][8 * nt + g], Vs[8 * ks + c + 4][8 * nt + g]);
        }
    }
    float inv0 = 1.f / l0, inv1 = 1.f / l1;
    int r0 = q0 + 16 * w + g, r1 = r0 + 8;
#pragma unroll
    for (int nt = 0; nt < 4; nt++) {
        int col = h * DD + 8 * nt + 2 * c;
        float2 v0 = {o[nt][0] * inv0, o[nt][1] * inv0};
        *(float2*)(g_att + ((size_t)(b * SS + r0)) * CS + col) = v0;
        float2 v1 = {o[nt][2] * inv1, o[nt][3] * inv1};
        *(float2*)(g_att + ((size_t)(b * SS + r1)) * CS + col) = v1;
    }
}

// ============================================================
// 7. out proj via tf32 mma: (g_att @ w_o + b_o) * gate
// ============================================================
__global__ __launch_bounds__(128) void proj_mma(const float* __restrict__ W,
                                                const float* __restrict__ b_o,
                                                float* __restrict__ out) {
    __shared__ unsigned As[64][40];
    __shared__ unsigned Bs[32][72];
    int n0 = blockIdx.x * 64, m0 = blockIdx.y * 64;
    int tid = threadIdx.x, w = tid >> 5, lane = tid & 31, g = lane >> 2, c = lane & 3;
    float acc[8][4] = {};

    for (int k0 = 0; k0 < CS; k0 += 32) {
        __syncthreads();
        for (int i = tid; i < 512; i += 128) {
            int r = i >> 3, c4 = (i & 7) * 4;
            float4 v = *(const float4*)(g_att + (size_t)(m0 + r) * CS + k0 + c4);
            uint4 u = {f2tf(v.x), f2tf(v.y), f2tf(v.z), f2tf(v.w)};
            *(uint4*)&As[r][c4] = u;
        }
        for (int i = tid; i < 512; i += 128) {
            int r = i >> 4, c4 = (i & 15) * 4;
            float4 v = *(const float4*)(W + (size_t)(k0 + r) * CS + n0 + c4);
            uint4 u = {f2tf(v.x), f2tf(v.y), f2tf(v.z), f2tf(v.w)};
            *(uint4*)&Bs[r][c4] = u;
        }
        __syncthreads();
#pragma unroll
        for (int ks = 0; ks < 4; ks++) {
            unsigned a[4] = {As[16 * w + g][8 * ks + c], As[16 * w + g + 8][8 * ks + c],
                             As[16 * w + g][8 * ks + c + 4], As[16 * w + g + 8][8 * ks + c + 4]};
#pragma unroll
            for (int nt = 0; nt < 8; nt++)
                mma8(acc[nt], a, Bs[8 * ks + c][8 * nt + g], Bs[8 * ks + c + 4][8 * nt + g]);
        }
    }
    int r0 = m0 + 16 * w + g, r1 = r0 + 8;
    int b = r0 >> 10;
    const float* gate = g_emb + b * 3 * CS + 2 * CS;
#pragma unroll
    for (int nt = 0; nt < 8; nt++) {
        int col = n0 + 8 * nt + 2 * c;
        float g0 = gate[col], g1 = gate[col + 1];
        float2 v0 = {(acc[nt][0] + b_o[col]) * g0, (acc[nt][1] + b_o[col + 1]) * g1};
        *(float2*)(out + (size_t)r0 * CS + col) = v0;
        float2 v1 = {(acc[nt][2] + b_o[col]) * g0, (acc[nt][3] + b_o[col + 1]) * g1};
        *(float2*)(out + (size_t)r1 * CS + col) = v1;
    }
}

// ============================================================
extern "C" void kernel_launch(void* const* d_in, const int* in_sizes, int n_in,
                              void* d_out, int out_size) {
    const float* bs      = (const float*)d_in[0];
    const float* z       = (const float*)d_in[1];
    const float* t       = (const float*)d_in[2];
    const float* beta    = (const float*)d_in[3];
    const int*   z_mask  = (const int*)  d_in[4];
    const float* w_adaln = (const float*)d_in[5];
    const float* b_adaln = (const float*)d_in[6];
    const float* ln_z_w  = (const float*)d_in[7];
    const float* ln_z_b  = (const float*)d_in[8];
    const float* w_q     = (const float*)d_in[9];
    const float* w_k     = (const float*)d_in[10];
    const float* w_v     = (const float*)d_in[11];
    const float* w_z     = (const float*)d_in[12];
    const float* rms_q_w = (const float*)d_in[13];
    const float* rms_k_w = (const float*)d_in[14];
    const float* w_o     = (const float*)d_in[15];
    const float* b_o     = (const float*)d_in[16];
    float* out = (float*)d_out;

    adaln_kernel<<<dim3(9, 2), 256>>>(t, w_adaln, b_adaln);
    bsnorm_kernel<<<NB * SS, 256>>>(bs);
    qkv_mma<<<dim3(36, 32), 128>>>(w_q, w_k, w_v);
    rms_kernel<<<12288, 256>>>(rms_q_w, rms_k_w);
    bias_kernel<<<SS, 256>>>(z, z_mask, beta, ln_z_w, ln_z_b, w_z);
    attn_mma<<<dim3(16, NH, NB), 128>>>();
    proj_mma<<<dim3(12, 32), 128>>>(w_o, b_o, out);
}

// round 3
// speedup vs baseline: 1.4708x; 1.1704x over previous
#include <cuda_runtime.h>
#include <math.h>
#include <stdint.h>

#define SS 1024
#define CS 768
#define CZ 128
#define NH 24
#define DD 32
#define NB 2

// ---- scratch ----
__device__ float g_emb[NB * 3 * CS];
__device__ float g_bsn[NB * SS * CS];
__device__ float g_qkv[3 * NB * NH * SS * DD];
__device__ float g_bias[(size_t)NH * SS * SS];     // (h,i,j)  ~100MB, no B dim
__device__ float g_att[NB * SS * CS];

__device__ __forceinline__ unsigned f2tf(float x) {
    unsigned u; asm("cvt.rna.tf32.f32 %0, %1;" : "=r"(u) : "f"(x)); return u;
}
__device__ __forceinline__ void mma8(float* c, const unsigned* a, unsigned b0, unsigned b1) {
    asm volatile("mma.sync.aligned.m16n8k8.row.col.f32.tf32.tf32.f32 "
        "{%0,%1,%2,%3},{%4,%5,%6,%7},{%8,%9},{%0,%1,%2,%3};"
        : "+f"(c[0]), "+f"(c[1]), "+f"(c[2]), "+f"(c[3])
        : "r"(a[0]), "r"(a[1]), "r"(a[2]), "r"(a[3]), "r"(b0), "r"(b1));
}

// ============================================================
// 1. adaLN
// ============================================================
__global__ void adaln_kernel(const float* __restrict__ t,
                             const float* __restrict__ w,
                             const float* __restrict__ bb) {
    int b = blockIdx.y;
    int n = blockIdx.x * 256 + threadIdx.x;
    __shared__ float st[CS];
    for (int c = threadIdx.x; c < CS; c += 256) {
        float v = t[b * CS + c];
        st[c] = v / (1.f + __expf(-v));
    }
    __syncthreads();
    float acc = bb[n];
#pragma unroll 4
    for (int c = 0; c < CS; c++) acc = fmaf(st[c], w[c * (3 * CS) + n], acc);
    g_emb[b * 3 * CS + n] = acc;
}

// ============================================================
// 2. bs LayerNorm + adaLN modulate
// ============================================================
__global__ void bsnorm_kernel(const float* __restrict__ bs) {
    int row = blockIdx.x;
    int b = row >> 10;
    const float* x = bs + (size_t)row * CS;
    int tid = threadIdx.x;
    float v0 = x[tid], v1 = x[tid + 256], v2 = x[tid + 512];

    __shared__ float red1[8], red2[8];
    float s = v0 + v1 + v2;
    for (int o = 16; o; o >>= 1) s += __shfl_xor_sync(~0u, s, o);
    if ((tid & 31) == 0) red1[tid >> 5] = s;
    __syncthreads();
    float tot = 0.f;
#pragma unroll
    for (int i = 0; i < 8; i++) tot += red1[i];
    float mu = tot * (1.f / CS);

    float d0 = v0 - mu, d1 = v1 - mu, d2 = v2 - mu;
    float q = d0 * d0 + d1 * d1 + d2 * d2;
    for (int o = 16; o; o >>= 1) q += __shfl_xor_sync(~0u, q, o);
    if ((tid & 31) == 0) red2[tid >> 5] = q;
    __syncthreads();
    float tot2 = 0.f;
#pragma unroll
    for (int i = 0; i < 8; i++) tot2 += red2[i];
    float rsig = rsqrtf(tot2 * (1.f / CS) + 1e-5f);

    const float* e = g_emb + b * 3 * CS;
    float* outp = g_bsn + (size_t)row * CS;
    outp[tid]       = d0 * rsig * (1.f + e[CS + tid])       + e[tid];
    outp[tid + 256] = d1 * rsig * (1.f + e[CS + tid + 256]) + e[tid + 256];
    outp[tid + 512] = d2 * rsig * (1.f + e[CS + tid + 512]) + e[tid + 512];
}

// ============================================================
// 3. QKV GEMM: BM=128 BN=128 BK=16, 256 thr, double-buffered,
//    warp tile m32 x n64, fused RMS(q,k) in epilogue
// ============================================================
__global__ __launch_bounds__(256) void qkv_mma2(const float* __restrict__ wq,
                                                const float* __restrict__ wk,
                                                const float* __restrict__ wv,
                                                const float* __restrict__ rqw,
                                                const float* __restrict__ rkw) {
    __shared__ unsigned As[2][128][20];
    __shared__ unsigned Bs[2][16][136];
    int tid = threadIdx.x, w = tid >> 5, lane = tid & 31, g = lane >> 2, c = lane & 3;
    int wm = w & 3, wn = w >> 2;
    int n0 = blockIdx.x * 128;
    int sel = n0 / CS, nc = n0 - sel * CS;
    const float* W = (sel == 0) ? wq : ((sel == 1) ? wk : wv);
    int m0 = blockIdx.y * 128;

    int arow = tid >> 1, acol = (tid & 1) * 8;
    int brow = tid >> 4, bcol = (tid & 15) * 8;
    const float* Ap = g_bsn + (size_t)(m0 + arow) * CS + acol;
    const float* Bp = W + (size_t)brow * CS + nc + bcol;

    float acc0[8][4] = {}, acc1[8][4] = {};
    float4 ra0 = *(const float4*)(Ap);
    float4 ra1 = *(const float4*)(Ap + 4);
    float4 rb0 = *(const float4*)(Bp);
    float4 rb1 = *(const float4*)(Bp + 4);
    {
        uint4 u;
        u.x = f2tf(ra0.x); u.y = f2tf(ra0.y); u.z = f2tf(ra0.z); u.w = f2tf(ra0.w);
        *(uint4*)&As[0][arow][acol] = u;
        u.x = f2tf(ra1.x); u.y = f2tf(ra1.y); u.z = f2tf(ra1.z); u.w = f2tf(ra1.w);
        *(uint4*)&As[0][arow][acol + 4] = u;
        u.x = f2tf(rb0.x); u.y = f2tf(rb0.y); u.z = f2tf(rb0.z); u.w = f2tf(rb0.w);
        *(uint4*)&Bs[0][brow][bcol] = u;
        u.x = f2tf(rb1.x); u.y = f2tf(rb1.y); u.z = f2tf(rb1.z); u.w = f2tf(rb1.w);
        *(uint4*)&Bs[0][brow][bcol + 4] = u;
    }
    __syncthreads();

    int buf = 0;
    for (int it = 0; it < 48; it++) {
        if (it < 47) {
            int kn = (it + 1) * 16;
            ra0 = *(const float4*)(Ap + kn);
            ra1 = *(const float4*)(Ap + kn + 4);
            rb0 = *(const float4*)(Bp + (size_t)kn * CS);
            rb1 = *(const float4*)(Bp + (size_t)kn * CS + 4);
        }
#pragma unroll
        for (int ks = 0; ks < 2; ks++) {
            int r0 = wm * 32 + g;
            unsigned a0[4] = {As[buf][r0][8 * ks + c], As[buf][r0 + 8][8 * ks + c],
                              As[buf][r0][8 * ks + c + 4], As[buf][r0 + 8][8 * ks + c + 4]};
            unsigned a1[4] = {As[buf][r0 + 16][8 * ks + c], As[buf][r0 + 24][8 * ks + c],
                              As[buf][r0 + 16][8 * ks + c + 4], As[buf][r0 + 24][8 * ks + c + 4]};
#pragma unroll
            for (int nt = 0; nt < 8; nt++) {
                unsigned b0 = Bs[buf][8 * ks + c][wn * 64 + 8 * nt + g];
                unsigned b1 = Bs[buf][8 * ks + c + 4][wn * 64 + 8 * nt + g];
                mma8(acc0[nt], a0, b0, b1);
                mma8(acc1[nt], a1, b0, b1);
            }
        }
        if (it < 47) {
            buf ^= 1;
            uint4 u;
            u.x = f2tf(ra0.x); u.y = f2tf(ra0.y); u.z = f2tf(ra0.z); u.w = f2tf(ra0.w);
            *(uint4*)&As[buf][arow][acol] = u;
            u.x = f2tf(ra1.x); u.y = f2tf(ra1.y); u.z = f2tf(ra1.z); u.w = f2tf(ra1.w);
            *(uint4*)&As[buf][arow][acol + 4] = u;
            u.x = f2tf(rb0.x); u.y = f2tf(rb0.y); u.z = f2tf(rb0.z); u.w = f2tf(rb0.w);
            *(uint4*)&Bs[buf][brow][bcol] = u;
            u.x = f2tf(rb1.x); u.y = f2tf(rb1.y); u.z = f2tf(rb1.z); u.w = f2tf(rb1.w);
            *(uint4*)&Bs[buf][brow][bcol + 4] = u;
            __syncthreads();
        }
    }

    // epilogue: scatter to (t,b,h,s,d) with fused RMS for q,k
    int bi = m0 >> 10;
    int r0g = m0 + wm * 32 + g;
#pragma unroll
    for (int mi = 0; mi < 2; mi++) {
        float (*ac)[4] = mi ? acc1 : acc0;
        int rb = r0g + mi * 16;
        int s0 = rb & 1023, s1 = s0 + 8;
#pragma unroll
        for (int hf = 0; hf < 2; hf++) {
            int h = (nc + wn * 64 + hf * 32) >> 5;
            float ss0 = 0.f, ss1 = 0.f;
#pragma unroll
            for (int nt = hf * 4; nt < hf * 4 + 4; nt++) {
                ss0 += ac[nt][0] * ac[nt][0] + ac[nt][1] * ac[nt][1];
                ss1 += ac[nt][2] * ac[nt][2] + ac[nt][3] * ac[nt][3];
            }
            float rs0 = 1.f, rs1 = 1.f;
            if (sel < 2) {
                ss0 += __shfl_xor_sync(~0u, ss0, 1); ss0 += __shfl_xor_sync(~0u, ss0, 2);
                ss1 += __shfl_xor_sync(~0u, ss1, 1); ss1 += __shfl_xor_sync(~0u, ss1, 2);
                rs0 = rsqrtf(ss0 * (1.f / 32) + 1e-5f);
                rs1 = rsqrtf(ss1 * (1.f / 32) + 1e-5f);
            }
            float* basep = g_qkv + ((size_t)(sel * NB + bi) * NH + h) * SS * DD;
            const float* wr = (sel == 0) ? rqw : rkw;
#pragma unroll
            for (int nt = hf * 4; nt < hf * 4 + 4; nt++) {
                int d = (8 * nt + 2 * c) & 31;
                float w0 = 1.f, w1 = 1.f;
                if (sel < 2) { w0 = wr[d]; w1 = wr[d + 1]; }
                float* p0 = basep + (size_t)s0 * DD + d;
                p0[0] = ac[nt][0] * rs0 * w0; p0[1] = ac[nt][1] * rs0 * w1;
                float* p1 = basep + (size_t)s1 * DD + d;
                p1[0] = ac[nt][2] * rs1 * w0; p1[1] = ac[nt][3] * rs1 * w1;
            }
        }
    }
}

// ============================================================
// 4. bias via tf32 mma: zpart[h,i,j] = LN(z[i,j])@W' (+mask)
//    CTA = (jtile 64, i), 128 threads, M=64 N=24 K=128
// ============================================================
__global__ __launch_bounds__(128) void bias_mma(const float* __restrict__ z,
                                                const int* __restrict__ zmask,
                                                const float* __restrict__ lnw,
                                                const float* __restrict__ lnb,
                                                const float* __restrict__ wz) {
    __shared__ unsigned Zs[64][132];
    __shared__ unsigned WT[24][132];
    __shared__ float muS[64], rsS[64], AhS[24], BhS[24];
    __shared__ int mS[64];
    int i = blockIdx.y, jt = blockIdx.x * 64;
    int tid = threadIdx.x, w = tid >> 5, lane = tid & 31, g = lane >> 2, c = lane & 3;

    for (int idx = tid; idx < 24 * 128; idx += 128) {
        int n = idx >> 7, k = idx & 127;
        WT[n][k] = f2tf(lnw[k] * wz[k * NH + n]);
    }
    if (tid < 64) mS[tid] = zmask[(size_t)i * SS + jt + tid];
    if (tid < NH) {
        float a = 0.f, bb = 0.f;
        for (int k = 0; k < CZ; k++) {
            float wv = wz[k * NH + tid];
            a += lnw[k] * wv; bb += lnb[k] * wv;
        }
        AhS[tid] = a; BhS[tid] = bb;
    }
    __syncthreads();

    // stage z rows (tf32) + stats; masked rows -> zeros (predicated loads)
    {
        int r = tid >> 1, hh = tid & 1;
        bool live = mS[r] != 0;
        const float4* zr = (const float4*)(z + ((size_t)i * SS + jt + r) * CZ + hh * 64);
        float s = 0.f, q = 0.f;
#pragma unroll
        for (int t = 0; t < 16; t++) {
            float4 v = live ? zr[t] : make_float4(0.f, 0.f, 0.f, 0.f);
            s += v.x + v.y + v.z + v.w;
            q += v.x * v.x + v.y * v.y + v.z * v.z + v.w * v.w;
            uint4 u = {f2tf(v.x), f2tf(v.y), f2tf(v.z), f2tf(v.w)};
            *(uint4*)&Zs[r][hh * 64 + t * 4] = u;
        }
        s += __shfl_xor_sync(~0u, s, 1);
        q += __shfl_xor_sync(~0u, q, 1);
        if (hh == 0) {
            float mu = s * (1.f / CZ);
            float var = q * (1.f / CZ) - mu * mu;
            muS[r] = mu;
            rsS[r] = rsqrtf(var + 1e-5f);
        }
    }
    __syncthreads();

    float acc[3][4] = {};
#pragma unroll
    for (int ks = 0; ks < 16; ks++) {
        unsigned a[4] = {Zs[16 * w + g][8 * ks + c], Zs[16 * w + g + 8][8 * ks + c],
                         Zs[16 * w + g][8 * ks + c + 4], Zs[16 * w + g + 8][8 * ks + c + 4]};
#pragma unroll
        for (int nt = 0; nt < 3; nt++)
            mma8(acc[nt], a, WT[8 * nt + g][8 * ks + c], WT[8 * nt + g][8 * ks + c + 4]);
    }

    int j0 = 16 * w + g, j1 = j0 + 8;
    float mu0 = muS[j0], rg0 = rsS[j0], mu1 = muS[j1], rg1 = rsS[j1];
    bool k0m = mS[j0] != 0, k1m = mS[j1] != 0;
#pragma unroll
    for (int nt = 0; nt < 3; nt++) {
        int h = 8 * nt + 2 * c;
        float A0 = AhS[h], B0 = BhS[h], A1 = AhS[h + 1], B1 = BhS[h + 1];
        size_t b0 = ((size_t)h * SS + i) * SS + jt;
        size_t b1 = ((size_t)(h + 1) * SS + i) * SS + jt;
        g_bias[b0 + j0] = k0m ? rg0 * (acc[nt][0] - mu0 * A0) + B0 : -1e9f;
        g_bias[b1 + j0] = k0m ? rg0 * (acc[nt][1] - mu0 * A1) + B1 : -1e9f;
        g_bias[b0 + j1] = k1m ? rg1 * (acc[nt][2] - mu1 * A0) + B0 : -1e9f;
        g_bias[b1 + j1] = k1m ? rg1 * (acc[nt][3] - mu1 * A1) + B1 : -1e9f;
    }
}

// ============================================================
// 5. flash attention via tf32 mma (beta folded at staging)
// ============================================================
__global__ __launch_bounds__(128) void attn_mma(const float* __restrict__ beta) {
    __shared__ unsigned Qs[64][40];
    __shared__ unsigned Ks[64][40];
    __shared__ unsigned Vs[64][40];
    __shared__ unsigned Ps[64][68];

    int b = blockIdx.z, h = blockIdx.y, q0 = blockIdx.x * 64;
    int tid = threadIdx.x, w = tid >> 5, lane = tid & 31, g = lane >> 2, c = lane & 3;

    const float* qptr = g_qkv + ((size_t)(0 * NB + b) * NH + h) * SS * DD;
    const float* kptr = g_qkv + ((size_t)(1 * NB + b) * NH + h) * SS * DD;
    const float* vptr = g_qkv + ((size_t)(2 * NB + b) * NH + h) * SS * DD;
    const float* zp = g_bias + ((size_t)h * SS + q0) * SS;
    const float* bp = beta + ((size_t)b * SS + q0) * SS;
    const float sc = 0.17677669529663687f;

    for (int i = tid; i < 512; i += 128) {
        int r = i >> 3, c4 = (i & 7) * 4;
        float4 v = *(const float4*)(qptr + (size_t)(q0 + r) * DD + c4);
        uint4 u = {f2tf(v.x * sc), f2tf(v.y * sc), f2tf(v.z * sc), f2tf(v.w * sc)};
        *(uint4*)&Qs[r][c4] = u;
    }
    __syncthreads();
    unsigned qa[4][4];
#pragma unroll
    for (int ks = 0; ks < 4; ks++) {
        qa[ks][0] = Qs[16 * w + g][8 * ks + c];
        qa[ks][1] = Qs[16 * w + g + 8][8 * ks + c];
        qa[ks][2] = Qs[16 * w + g][8 * ks + c + 4];
        qa[ks][3] = Qs[16 * w + g + 8][8 * ks + c + 4];
    }
    float mr0 = -1e30f, mr1 = -1e30f, l0 = 0.f, l1 = 0.f;
    float o[4][4] = {};

    for (int kt = 0; kt < 16; kt++) {
        int k0 = kt * 64;
        __syncthreads();
        for (int i = tid; i < 512; i += 128) {
            int r = i >> 3, c4 = (i & 7) * 4;
            float4 kv = *(const float4*)(kptr + (size_t)(k0 + r) * DD + c4);
            uint4 u = {f2tf(kv.x), f2tf(kv.y), f2tf(kv.z), f2tf(kv.w)};
            *(uint4*)&Ks[r][c4] = u;
            float4 vv = *(const float4*)(vptr + (size_t)(k0 + r) * DD + c4);
            uint4 u2 = {f2tf(vv.x), f2tf(vv.y), f2tf(vv.z), f2tf(vv.w)};
            *(uint4*)&Vs[r][c4] = u2;
        }
        for (int i = tid; i < 1024; i += 128) {
            int r = i >> 4, c4 = (i & 15) * 4;
            float4 zb = *(const float4*)(zp + (size_t)r * SS + k0 + c4);
            float4 bt = *(const float4*)(bp + (size_t)r * SS + k0 + c4);
            zb.x += bt.x; zb.y += bt.y; zb.z += bt.z; zb.w += bt.w;
            *(float4*)&Ps[r][c4] = zb;
        }
        __syncthreads();

        float s[8][4] = {};
#pragma unroll
        for (int ks = 0; ks < 4; ks++) {
#pragma unroll
            for (int nt = 0; nt < 8; nt++)
                mma8(s[nt], qa[ks], Ks[8 * nt + g][8 * ks + c], Ks[8 * nt + g][8 * ks + c + 4]);
        }
        float mx0 = -1e30f, mx1 = -1e30f;
#pragma unroll
        for (int nt = 0; nt < 8; nt++) {
            s[nt][0] += __uint_as_float(Ps[16 * w + g][8 * nt + 2 * c]);
            s[nt][1] += __uint_as_float(Ps[16 * w + g][8 * nt + 2 * c + 1]);
            s[nt][2] += __uint_as_float(Ps[16 * w + g + 8][8 * nt + 2 * c]);
            s[nt][3] += __uint_as_float(Ps[16 * w + g + 8][8 * nt + 2 * c + 1]);
            mx0 = fmaxf(mx0, fmaxf(s[nt][0], s[nt][1]));
            mx1 = fmaxf(mx1, fmaxf(s[nt][2], s[nt][3]));
        }
        mx0 = fmaxf(mx0, __shfl_xor_sync(~0u, mx0, 1));
        mx0 = fmaxf(mx0, __shfl_xor_sync(~0u, mx0, 2));
        mx1 = fmaxf(mx1, __shfl_xor_sync(~0u, mx1, 1));
        mx1 = fmaxf(mx1, __shfl_xor_sync(~0u, mx1, 2));
        float mn0 = fmaxf(mr0, mx0), mn1 = fmaxf(mr1, mx1);
        float a0 = __expf(mr0 - mn0), a1 = __expf(mr1 - mn1);
        float rs0 = 0.f, rs1 = 0.f;
#pragma unroll
        for (int nt = 0; nt < 8; nt++) {
            float e0 = __expf(s[nt][0] - mn0), e1 = __expf(s[nt][1] - mn0);
            float e2 = __expf(s[nt][2] - mn1), e3 = __expf(s[nt][3] - mn1);
            rs0 += e0 + e1; rs1 += e2 + e3;
            uint2 u0 = {f2tf(e0), f2tf(e1)};
            *(uint2*)&Ps[16 * w + g][8 * nt + 2 * c] = u0;
            uint2 u1 = {f2tf(e2), f2tf(e3)};
            *(uint2*)&Ps[16 * w + g + 8][8 * nt + 2 * c] = u1;
        }
        rs0 += __shfl_xor_sync(~0u, rs0, 1); rs0 += __shfl_xor_sync(~0u, rs0, 2);
        rs1 += __shfl_xor_sync(~0u, rs1, 1); rs1 += __shfl_xor_sync(~0u, rs1, 2);
        l0 = l0 * a0 + rs0; l1 = l1 * a1 + rs1;
        mr0 = mn0; mr1 = mn1;
#pragma unroll
        for (int nt = 0; nt < 4; nt++) {
            o[nt][0] *= a0; o[nt][1] *= a0; o[nt][2] *= a1; o[nt][3] *= a1;
        }
        __syncwarp();
#pragma unroll
        for (int ks = 0; ks < 8; ks++) {
            unsigned pa[4] = {Ps[16 * w + g][8 * ks + c], Ps[16 * w + g + 8][8 * ks + c],
                              Ps[16 * w + g][8 * ks + c + 4], Ps[16 * w + g + 8][8 * ks + c + 4]};
#pragma unroll
            for (int nt = 0; nt < 4; nt++)
                mma8(o[nt], pa, Vs[8 * ks + c][8 * nt + g], Vs[8 * ks + c + 4][8 * nt + g]);
        }
    }
    float inv0 = 1.f / l0, inv1 = 1.f / l1;
    int r0 = q0 + 16 * w + g, r1 = r0 + 8;
#pragma unroll
    for (int nt = 0; nt < 4; nt++) {
        int col = h * DD + 8 * nt + 2 * c;
        float2 v0 = {o[nt][0] * inv0, o[nt][1] * inv0};
        *(float2*)(g_att + ((size_t)(b * SS + r0)) * CS + col) = v0;
        float2 v1 = {o[nt][2] * inv1, o[nt][3] * inv1};
        *(float2*)(g_att + ((size_t)(b * SS + r1)) * CS + col) = v1;
    }
}

// ============================================================
// 6. out proj: BM=128 BN=128 BK=16 double-buffered
// ============================================================
__global__ __launch_bounds__(256) void proj_mma2(const float* __restrict__ W,
                                                 const float* __restrict__ b_o,
                                                 float* __restrict__ out) {
    __shared__ unsigned As[2][128][20];
    __shared__ unsigned Bs[2][16][136];
    int tid = threadIdx.x, w = tid >> 5, lane = tid & 31, g = lane >> 2, c = lane & 3;
    int wm = w & 3, wn = w >> 2;
    int n0 = blockIdx.x * 128, m0 = blockIdx.y * 128;

    int arow = tid >> 1, acol = (tid & 1) * 8;
    int brow = tid >> 4, bcol = (tid & 15) * 8;
    const float* Ap = g_att + (size_t)(m0 + arow) * CS + acol;
    const float* Bp = W + (size_t)brow * CS + n0 + bcol;

    float acc0[8][4] = {}, acc1[8][4] = {};
    float4 ra0 = *(const float4*)(Ap);
    float4 ra1 = *(const float4*)(Ap + 4);
    float4 rb0 = *(const float4*)(Bp);
    float4 rb1 = *(const float4*)(Bp + 4);
    {
        uint4 u;
        u.x = f2tf(ra0.x); u.y = f2tf(ra0.y); u.z = f2tf(ra0.z); u.w = f2tf(ra0.w);
        *(uint4*)&As[0][arow][acol] = u;
        u.x = f2tf(ra1.x); u.y = f2tf(ra1.y); u.z = f2tf(ra1.z); u.w = f2tf(ra1.w);
        *(uint4*)&As[0][arow][acol + 4] = u;
        u.x = f2tf(rb0.x); u.y = f2tf(rb0.y); u.z = f2tf(rb0.z); u.w = f2tf(rb0.w);
        *(uint4*)&Bs[0][brow][bcol] = u;
        u.x = f2tf(rb1.x); u.y = f2tf(rb1.y); u.z = f2tf(rb1.z); u.w = f2tf(rb1.w);
        *(uint4*)&Bs[0][brow][bcol + 4] = u;
    }
    __syncthreads();

    int buf = 0;
    for (int it = 0; it < 48; it++) {
        if (it < 47) {
            int kn = (it + 1) * 16;
            ra0 = *(const float4*)(Ap + kn);
            ra1 = *(const float4*)(Ap + kn + 4);
            rb0 = *(const float4*)(Bp + (size_t)kn * CS);
            rb1 = *(const float4*)(Bp + (size_t)kn * CS + 4);
        }
#pragma unroll
        for (int ks = 0; ks < 2; ks++) {
            int r0 = wm * 32 + g;
            unsigned a0[4] = {As[buf][r0][8 * ks + c], As[buf][r0 + 8][8 * ks + c],
                              As[buf][r0][8 * ks + c + 4], As[buf][r0 + 8][8 * ks + c + 4]};
            unsigned a1[4] = {As[buf][r0 + 16][8 * ks + c], As[buf][r0 + 24][8 * ks + c],
                              As[buf][r0 + 16][8 * ks + c + 4], As[buf][r0 + 24][8 * ks + c + 4]};
#pragma unroll
            for (int nt = 0; nt < 8; nt++) {
                unsigned b0 = Bs[buf][8 * ks + c][wn * 64 + 8 * nt + g];
                unsigned b1 = Bs[buf][8 * ks + c + 4][wn * 64 + 8 * nt + g];
                mma8(acc0[nt], a0, b0, b1);
                mma8(acc1[nt], a1, b0, b1);
            }
        }
        if (it < 47) {
            buf ^= 1;
            uint4 u;
            u.x = f2tf(ra0.x); u.y = f2tf(ra0.y); u.z = f2tf(ra0.z); u.w = f2tf(ra0.w);
            *(uint4*)&As[buf][arow][acol] = u;
            u.x = f2tf(ra1.x); u.y = f2tf(ra1.y); u.z = f2tf(ra1.z); u.w = f2tf(ra1.w);
            *(uint4*)&As[buf][arow][acol + 4] = u;
            u.x = f2tf(rb0.x); u.y = f2tf(rb0.y); u.z = f2tf(rb0.z); u.w = f2tf(rb0.w);
            *(uint4*)&Bs[buf][brow][bcol] = u;
            u.x = f2tf(rb1.x); u.y = f2tf(rb1.y); u.z = f2tf(rb1.z); u.w = f2tf(rb1.w);
            *(uint4*)&Bs[buf][brow][bcol + 4] = u;
            __syncthreads();
        }
    }

    int bi = m0 >> 10;
    const float* gate = g_emb + bi * 3 * CS + 2 * CS;
    int r0g = m0 + wm * 32 + g;
#pragma unroll
    for (int mi = 0; mi < 2; mi++) {
        float (*ac)[4] = mi ? acc1 : acc0;
        int rb = r0g + mi * 16;
#pragma unroll
        for (int nt = 0; nt < 8; nt++) {
            int col = n0 + wn * 64 + 8 * nt + 2 * c;
            float g0 = gate[col], g1 = gate[col + 1];
            float bo0 = b_o[col], bo1 = b_o[col + 1];
            float2 v0 = {(ac[nt][0] + bo0) * g0, (ac[nt][1] + bo1) * g1};
            *(float2*)(out + (size_t)rb * CS + col) = v0;
            float2 v1 = {(ac[nt][2] + bo0) * g0, (ac[nt][3] + bo1) * g1};
            *(float2*)(out + (size_t)(rb + 8) * CS + col) = v1;
        }
    }
}

// ============================================================
extern "C" void kernel_launch(void* const* d_in, const int* in_sizes, int n_in,
                              void* d_out, int out_size) {
    const float* bs      = (const float*)d_in[0];
    const float* z       = (const float*)d_in[1];
    const float* t       = (const float*)d_in[2];
    const float* beta    = (const float*)d_in[3];
    const int*   z_mask  = (const int*)  d_in[4];
    const float* w_adaln = (const float*)d_in[5];
    const float* b_adaln = (const float*)d_in[6];
    const float* ln_z_w  = (const float*)d_in[7];
    const float* ln_z_b  = (const float*)d_in[8];
    const float* w_q     = (const float*)d_in[9];
    const float* w_k     = (const float*)d_in[10];
    const float* w_v     = (const float*)d_in[11];
    const float* w_z     = (const float*)d_in[12];
    const float* rms_q_w = (const float*)d_in[13];
    const float* rms_k_w = (const float*)d_in[14];
    const float* w_o     = (const float*)d_in[15];
    const float* b_o     = (const float*)d_in[16];
    float* out = (float*)d_out;

    adaln_kernel<<<dim3(9, 2), 256>>>(t, w_adaln, b_adaln);
    bsnorm_kernel<<<NB * SS, 256>>>(bs);
    bias_mma<<<dim3(16, SS), 128>>>(z, z_mask, ln_z_w, ln_z_b, w_z);
    qkv_mma2<<<dim3(18, 16), 256>>>(w_q, w_k, w_v, rms_q_w, rms_k_w);
    attn_mma<<<dim3(16, NH, NB), 128>>>(beta);
    proj_mma2<<<dim3(6, 16), 256>>>(w_o, b_o, out);
}

// round 5
// speedup vs baseline: 1.5532x; 1.0560x over previous
#include <cuda_runtime.h>
#include <math.h>
#include <stdint.h>

#define SS 1024
#define CS 768
#define CZ 128
#define NH 24
#define DD 32
#define NB 2
#define L2E 1.4426950408889634f

// ---- scratch ----
__device__ float    g_emb[NB * 3 * CS];
__device__ unsigned g_bsn[NB * SS * CS];                 // tf32 bits
__device__ unsigned g_qkv[3 * NB * NH * SS * DD];        // tf32 bits (q pre-scaled, rms folded)
__device__ float    g_bias[(size_t)NH * SS * SS];        // (h,i,j) fp32
__device__ unsigned g_att[NB * SS * CS];                 // tf32 bits
__device__ unsigned g_w[4][CS * CS];                     // tf32 wq,wk,wv,wo

__device__ __forceinline__ unsigned f2tf(float x) {
    unsigned u; asm("cvt.rna.tf32.f32 %0, %1;" : "=r"(u) : "f"(x)); return u;
}
__device__ __forceinline__ void mma8(float* c, const unsigned* a, unsigned b0, unsigned b1) {
    asm volatile("mma.sync.aligned.m16n8k8.row.col.f32.tf32.tf32.f32 "
        "{%0,%1,%2,%3},{%4,%5,%6,%7},{%8,%9},{%0,%1,%2,%3};"
        : "+f"(c[0]), "+f"(c[1]), "+f"(c[2]), "+f"(c[3])
        : "r"(a[0]), "r"(a[1]), "r"(a[2]), "r"(a[3]), "r"(b0), "r"(b1));
}
__device__ __forceinline__ void cpa16(void* s, const void* g) {
    asm volatile("cp.async.cg.shared.global [%0], [%1], 16;"
                 :: "r"((unsigned)__cvta_generic_to_shared(s)), "l"(g));
}
__device__ __forceinline__ void cp_commit() { asm volatile("cp.async.commit_group;"); }
__device__ __forceinline__ void cp_wait0()  { asm volatile("cp.async.wait_group 0;"); }
__device__ __forceinline__ void cp_wait1()  { asm volatile("cp.async.wait_group 1;"); }

// fast 2^y on fma pipe; caller clamps y >= -126
__device__ __forceinline__ float fexp2(float y) {
    float t = y + 12582912.f;                 // round-to-int magic
    int ei = __float_as_int(t) << 23;
    float f = y - (t - 12582912.f);           // f in [-0.5, 0.5]
    float p = 0.0013333558f;
    p = fmaf(p, f, 0.0096181291f);
    p = fmaf(p, f, 0.0555041087f);
    p = fmaf(p, f, 0.2402265069f);
    p = fmaf(p, f, 0.6931471806f);
    p = fmaf(p, f, 1.f);
    return __int_as_float(__float_as_int(p) + ei);
}

// ============================================================
// 0. weight pre-convert to tf32
// ============================================================
__global__ void wconv_kernel(const float* __restrict__ wq, const float* __restrict__ wk,
                             const float* __restrict__ wv, const float* __restrict__ wo) {
    int i4 = (blockIdx.x * 256 + threadIdx.x) * 4;
    if (i4 >= CS * CS) return;
    const float* src[4] = {wq, wk, wv, wo};
#pragma unroll
    for (int a = 0; a < 4; a++) {
        float4 v = *(const float4*)(src[a] + i4);
        uint4 u = {f2tf(v.x), f2tf(v.y), f2tf(v.z), f2tf(v.w)};
        *(uint4*)&g_w[a][i4] = u;
    }
}

// ============================================================
// 1. adaLN
// ============================================================
__global__ void adaln_kernel(const float* __restrict__ t,
                             const float* __restrict__ w,
                             const float* __restrict__ bb) {
    int b = blockIdx.y;
    int n = blockIdx.x * 256 + threadIdx.x;
    __shared__ float st[CS];
    for (int c = threadIdx.x; c < CS; c += 256) {
        float v = t[b * CS + c];
        st[c] = v / (1.f + __expf(-v));
    }
    __syncthreads();
    float acc = bb[n];
#pragma unroll 4
    for (int c = 0; c < CS; c++) acc = fmaf(st[c], w[c * (3 * CS) + n], acc);
    g_emb[b * 3 * CS + n] = acc;
}

// ============================================================
// 2. bs LayerNorm + adaLN modulate -> tf32 g_bsn
// ============================================================
__global__ void bsnorm_kernel(const float* __restrict__ bs) {
    int row = blockIdx.x;
    int b = row >> 10;
    const float* x = bs + (size_t)row * CS;
    int tid = threadIdx.x;
    float v0 = x[tid], v1 = x[tid + 256], v2 = x[tid + 512];

    __shared__ float red1[8], red2[8];
    float s = v0 + v1 + v2;
    for (int o = 16; o; o >>= 1) s += __shfl_xor_sync(~0u, s, o);
    if ((tid & 31) == 0) red1[tid >> 5] = s;
    __syncthreads();
    float tot = 0.f;
#pragma unroll
    for (int i = 0; i < 8; i++) tot += red1[i];
    float mu = tot * (1.f / CS);

    float d0 = v0 - mu, d1 = v1 - mu, d2 = v2 - mu;
    float q = d0 * d0 + d1 * d1 + d2 * d2;
    for (int o = 16; o; o >>= 1) q += __shfl_xor_sync(~0u, q, o);
    if ((tid & 31) == 0) red2[tid >> 5] = q;
    __syncthreads();
    float tot2 = 0.f;
#pragma unroll
    for (int i = 0; i < 8; i++) tot2 += red2[i];
    float rsig = rsqrtf(tot2 * (1.f / CS) + 1e-5f);

    const float* e = g_emb + b * 3 * CS;
    unsigned* outp = g_bsn + (size_t)row * CS;
    outp[tid]       = f2tf(d0 * rsig * (1.f + e[CS + tid])       + e[tid]);
    outp[tid + 256] = f2tf(d1 * rsig * (1.f + e[CS + tid + 256]) + e[tid + 256]);
    outp[tid + 512] = f2tf(d2 * rsig * (1.f + e[CS + tid + 512]) + e[tid + 512]);
}

// ============================================================
// 3. QKV GEMM, cp.async double-buffered, fused RMS + q-scale
// ============================================================
__global__ __launch_bounds__(256) void qkv_mma2(const float* __restrict__ rqw,
                                                const float* __restrict__ rkw) {
    __shared__ unsigned As[2][128][20];
    __shared__ unsigned Bs[2][16][136];
    int tid = threadIdx.x, w = tid >> 5, lane = tid & 31, g = lane >> 2, c = lane & 3;
    int wm = w & 3, wn = w >> 2;
    int n0 = blockIdx.x * 128;
    int sel = n0 / CS, nc = n0 - sel * CS;
    const unsigned* W = g_w[sel];
    int m0 = blockIdx.y * 128;

    float acc0[8][4] = {}, acc1[8][4] = {};

    // prologue: stage k=0 into buf 0
#pragma unroll
    for (int i = 0; i < 2; i++) {
        int ch = tid * 2 + i;
        int ar = ch >> 2, ac = (ch & 3) * 4;
        cpa16(&As[0][ar][ac], g_bsn + (size_t)(m0 + ar) * CS + ac);
        int br = ch >> 5, bc = (ch & 31) * 4;
        cpa16(&Bs[0][br][bc], W + (size_t)br * CS + nc + bc);
    }
    cp_commit(); cp_wait0();
    __syncthreads();

    int buf = 0;
    for (int it = 0; it < 48; it++) {
        if (it < 47) {
            int kn = (it + 1) * 16;
#pragma unroll
            for (int i = 0; i < 2; i++) {
                int ch = tid * 2 + i;
                int ar = ch >> 2, ac = (ch & 3) * 4;
                cpa16(&As[buf ^ 1][ar][ac], g_bsn + (size_t)(m0 + ar) * CS + kn + ac);
                int br = ch >> 5, bc = (ch & 31) * 4;
                cpa16(&Bs[buf ^ 1][br][bc], W + (size_t)(kn + br) * CS + nc + bc);
            }
            cp_commit();
        }
#pragma unroll
        for (int ks = 0; ks < 2; ks++) {
            int r0 = wm * 32 + g;
            unsigned a0[4] = {As[buf][r0][8 * ks + c], As[buf][r0 + 8][8 * ks + c],
                              As[buf][r0][8 * ks + c + 4], As[buf][r0 + 8][8 * ks + c + 4]};
            unsigned a1[4] = {As[buf][r0 + 16][8 * ks + c], As[buf][r0 + 24][8 * ks + c],
                              As[buf][r0 + 16][8 * ks + c + 4], As[buf][r0 + 24][8 * ks + c + 4]};
#pragma unroll
            for (int nt = 0; nt < 8; nt++) {
                unsigned b0 = Bs[buf][8 * ks + c][wn * 64 + 8 * nt + g];
                unsigned b1 = Bs[buf][8 * ks + c + 4][wn * 64 + 8 * nt + g];
                mma8(acc0[nt], a0, b0, b1);
                mma8(acc1[nt], a1, b0, b1);
            }
        }
        if (it < 47) {
            cp_wait0();
            __syncthreads();
            buf ^= 1;
        }
    }

    // epilogue: fused RMS (q,k), q * 1/sqrt(D); scatter tf32 to (t,b,h,s,d)
    const float SC = 0.17677669529663687f;
    int bi = m0 >> 10;
    int r0g = m0 + wm * 32 + g;
#pragma unroll
    for (int mi = 0; mi < 2; mi++) {
        float (*ac)[4] = mi ? acc1 : acc0;
        int rb = r0g + mi * 16;
        int s0 = rb & 1023, s1 = s0 + 8;
#pragma unroll
        for (int hf = 0; hf < 2; hf++) {
            int h = (nc + wn * 64 + hf * 32) >> 5;
            float ss0 = 0.f, ss1 = 0.f;
#pragma unroll
            for (int nt = hf * 4; nt < hf * 4 + 4; nt++) {
                ss0 += ac[nt][0] * ac[nt][0] + ac[nt][1] * ac[nt][1];
                ss1 += ac[nt][2] * ac[nt][2] + ac[nt][3] * ac[nt][3];
            }
            float rs0 = 1.f, rs1 = 1.f;
            if (sel < 2) {
                ss0 += __shfl_xor_sync(~0u, ss0, 1); ss0 += __shfl_xor_sync(~0u, ss0, 2);
                ss1 += __shfl_xor_sync(~0u, ss1, 1); ss1 += __shfl_xor_sync(~0u, ss1, 2);
                rs0 = rsqrtf(ss0 * (1.f / 32) + 1e-5f);
                rs1 = rsqrtf(ss1 * (1.f / 32) + 1e-5f);
                if (sel == 0) { rs0 *= SC; rs1 *= SC; }
            }
            unsigned* basep = g_qkv + ((size_t)(sel * NB + bi) * NH + h) * SS * DD;
            const float* wr = (sel == 0) ? rqw : rkw;
#pragma unroll
            for (int nt = hf * 4; nt < hf * 4 + 4; nt++) {
                int d = (8 * nt + 2 * c) & 31;
                float w0 = 1.f, w1 = 1.f;
                if (sel < 2) { w0 = wr[d]; w1 = wr[d + 1]; }
                unsigned* p0 = basep + (size_t)s0 * DD + d;
                p0[0] = f2tf(ac[nt][0] * rs0 * w0); p0[1] = f2tf(ac[nt][1] * rs0 * w1);
                unsigned* p1 = basep + (size_t)s1 * DD + d;
                p1[0] = f2tf(ac[nt][2] * rs1 * w0); p1[1] = f2tf(ac[nt][3] * rs1 * w1);
            }
        }
    }
}

// ============================================================
// 4. bias via tf32 mma (unchanged from R3)
// ============================================================
__global__ __launch_bounds__(128) void bias_mma(const float* __restrict__ z,
                                                const int* __restrict__ zmask,
                                                const float* __restrict__ lnw,
                                                const float* __restrict__ lnb,
                                                const float* __restrict__ wz) {
    __shared__ unsigned Zs[64][132];
    __shared__ unsigned WT[24][132];
    __shared__ float muS[64], rsS[64], AhS[24], BhS[24];
    __shared__ int mS[64];
    int i = blockIdx.y, jt = blockIdx.x * 64;
    int tid = threadIdx.x, w = tid >> 5, lane = tid & 31, g = lane >> 2, c = lane & 3;

    for (int idx = tid; idx < 24 * 128; idx += 128) {
        int n = idx >> 7, k = idx & 127;
        WT[n][k] = f2tf(lnw[k] * wz[k * NH + n]);
    }
    if (tid < 64) mS[tid] = zmask[(size_t)i * SS + jt + tid];
    if (tid < NH) {
        float a = 0.f, bb = 0.f;
        for (int k = 0; k < CZ; k++) {
            float wv = wz[k * NH + tid];
            a += lnw[k] * wv; bb += lnb[k] * wv;
        }
        AhS[tid] = a; BhS[tid] = bb;
    }
    __syncthreads();

    {
        int r = tid >> 1, hh = tid & 1;
        bool live = mS[r] != 0;
        const float4* zr = (const float4*)(z + ((size_t)i * SS + jt + r) * CZ + hh * 64);
        float s = 0.f, q = 0.f;
#pragma unroll
        for (int t = 0; t < 16; t++) {
            float4 v = live ? zr[t] : make_float4(0.f, 0.f, 0.f, 0.f);
            s += v.x + v.y + v.z + v.w;
            q += v.x * v.x + v.y * v.y + v.z * v.z + v.w * v.w;
            uint4 u = {f2tf(v.x), f2tf(v.y), f2tf(v.z), f2tf(v.w)};
            *(uint4*)&Zs[r][hh * 64 + t * 4] = u;
        }
        s += __shfl_xor_sync(~0u, s, 1);
        q += __shfl_xor_sync(~0u, q, 1);
        if (hh == 0) {
            float mu = s * (1.f / CZ);
            float var = q * (1.f / CZ) - mu * mu;
            muS[r] = mu;
            rsS[r] = rsqrtf(var + 1e-5f);
        }
    }
    __syncthreads();

    float acc[3][4] = {};
#pragma unroll
    for (int ks = 0; ks < 16; ks++) {
        unsigned a[4] = {Zs[16 * w + g][8 * ks + c], Zs[16 * w + g + 8][8 * ks + c],
                         Zs[16 * w + g][8 * ks + c + 4], Zs[16 * w + g + 8][8 * ks + c + 4]};
#pragma unroll
        for (int nt = 0; nt < 3; nt++)
            mma8(acc[nt], a, WT[8 * nt + g][8 * ks + c], WT[8 * nt + g][8 * ks + c + 4]);
    }

    int j0 = 16 * w + g, j1 = j0 + 8;
    float mu0 = muS[j0], rg0 = rsS[j0], mu1 = muS[j1], rg1 = rsS[j1];
    bool k0m = mS[j0] != 0, k1m = mS[j1] != 0;
#pragma unroll
    for (int nt = 0; nt < 3; nt++) {
        int h = 8 * nt + 2 * c;
        float A0 = AhS[h], B0 = BhS[h], A1 = AhS[h + 1], B1 = BhS[h + 1];
        size_t b0 = ((size_t)h * SS + i) * SS + jt;
        size_t b1 = ((size_t)(h + 1) * SS + i) * SS + jt;
        g_bias[b0 + j0] = k0m ? rg0 * (acc[nt][0] - mu0 * A0) + B0 : -1e9f;
        g_bias[b1 + j0] = k0m ? rg0 * (acc[nt][1] - mu0 * A1) + B1 : -1e9f;
        g_bias[b0 + j1] = k1m ? rg1 * (acc[nt][2] - mu1 * A0) + B0 : -1e9f;
        g_bias[b1 + j1] = k1m ? rg1 * (acc[nt][3] - mu1 * A1) + B1 : -1e9f;
    }
}

// ============================================================
// 5. flash attention: q-tile 128, 256 thr, cp.async K/V double
//    buffer, fma-pipe exp
// ============================================================
struct AttnSmem {
    unsigned Qs[128][36];
    unsigned Ks[2][64][36];
    unsigned Vs[2][64][40];
    float    Ps[128][68];
};

__global__ __launch_bounds__(256) void attn_mma(const float* __restrict__ beta) {
    extern __shared__ char smem_raw[];
    AttnSmem* sm = (AttnSmem*)smem_raw;
    int b = blockIdx.z, h = blockIdx.y, q0 = blockIdx.x * 128;
    int tid = threadIdx.x, w = tid >> 5, lane = tid & 31, g = lane >> 2, c = lane & 3;

    const unsigned* qptr = g_qkv + ((size_t)(0 * NB + b) * NH + h) * SS * DD;
    const unsigned* kptr = g_qkv + ((size_t)(1 * NB + b) * NH + h) * SS * DD;
    const unsigned* vptr = g_qkv + ((size_t)(2 * NB + b) * NH + h) * SS * DD;
    const float* zp = g_bias + ((size_t)h * SS + q0) * SS;
    const float* bp = beta + ((size_t)b * SS + q0) * SS;

    // stage Q (1024 chunks) + K/V tile 0 (512 chunks each)
#pragma unroll
    for (int i = 0; i < 4; i++) {
        int ch = tid + 256 * i;
        int r = ch >> 3, col = (ch & 7) * 4;
        cpa16(&sm->Qs[r][col], qptr + (size_t)(q0 + r) * DD + col);
    }
#pragma unroll
    for (int i = 0; i < 2; i++) {
        int ch = tid + 256 * i;
        int r = ch >> 3, col = (ch & 7) * 4;
        cpa16(&sm->Ks[0][r][col], kptr + (size_t)r * DD + col);
        cpa16(&sm->Vs[0][r][col], vptr + (size_t)r * DD + col);
    }
    cp_commit(); cp_wait0();
    __syncthreads();

    unsigned qa[4][4];
#pragma unroll
    for (int ks = 0; ks < 4; ks++) {
        qa[ks][0] = sm->Qs[16 * w + g][8 * ks + c];
        qa[ks][1] = sm->Qs[16 * w + g + 8][8 * ks + c];
        qa[ks][2] = sm->Qs[16 * w + g][8 * ks + c + 4];
        qa[ks][3] = sm->Qs[16 * w + g + 8][8 * ks + c + 4];
    }
    float mr0 = -1e30f, mr1 = -1e30f, l0 = 0.f, l1 = 0.f;
    float o[4][4] = {};

    int buf = 0;
    for (int kt = 0; kt < 16; kt++) {
        int k0 = kt * 64;
        if (kt < 15) {
            int kn = k0 + 64;
#pragma unroll
            for (int i = 0; i < 2; i++) {
                int ch = tid + 256 * i;
                int r = ch >> 3, col = (ch & 7) * 4;
                cpa16(&sm->Ks[buf ^ 1][r][col], kptr + (size_t)(kn + r) * DD + col);
                cpa16(&sm->Vs[buf ^ 1][r][col], vptr + (size_t)(kn + r) * DD + col);
            }
            cp_commit();
        }
        // stage bias + beta -> Ps
        for (int idx = tid; idx < 2048; idx += 256) {
            int r = idx >> 4, c4 = (idx & 15) * 4;
            float4 zb = *(const float4*)(zp + (size_t)r * SS + k0 + c4);
            float4 bt = *(const float4*)(bp + (size_t)r * SS + k0 + c4);
            zb.x += bt.x; zb.y += bt.y; zb.z += bt.z; zb.w += bt.w;
            *(float4*)&sm->Ps[r][c4] = zb;
        }
        if (kt < 15) cp_wait1(); else cp_wait0();
        __syncthreads();

        float s[8][4] = {};
#pragma unroll
        for (int ks = 0; ks < 4; ks++) {
#pragma unroll
            for (int nt = 0; nt < 8; nt++)
                mma8(s[nt], qa[ks], sm->Ks[buf][8 * nt + g][8 * ks + c],
                                    sm->Ks[buf][8 * nt + g][8 * ks + c + 4]);
        }
        float mx0 = -1e30f, mx1 = -1e30f;
#pragma unroll
        for (int nt = 0; nt < 8; nt++) {
            s[nt][0] += sm->Ps[16 * w + g][8 * nt + 2 * c];
            s[nt][1] += sm->Ps[16 * w + g][8 * nt + 2 * c + 1];
            s[nt][2] += sm->Ps[16 * w + g + 8][8 * nt + 2 * c];
            s[nt][3] += sm->Ps[16 * w + g + 8][8 * nt + 2 * c + 1];
            mx0 = fmaxf(mx0, fmaxf(s[nt][0], s[nt][1]));
            mx1 = fmaxf(mx1, fmaxf(s[nt][2], s[nt][3]));
        }
        mx0 = fmaxf(mx0, __shfl_xor_sync(~0u, mx0, 1));
        mx0 = fmaxf(mx0, __shfl_xor_sync(~0u, mx0, 2));
        mx1 = fmaxf(mx1, __shfl_xor_sync(~0u, mx1, 1));
        mx1 = fmaxf(mx1, __shfl_xor_sync(~0u, mx1, 2));
        float mn0 = fmaxf(mr0, mx0), mn1 = fmaxf(mr1, mx1);
        float a0 = fexp2(fmaxf((mr0 - mn0) * L2E, -126.f));
        float a1 = fexp2(fmaxf((mr1 - mn1) * L2E, -126.f));
        float m20 = mn0 * L2E, m21 = mn1 * L2E;
        float rs0 = 0.f, rs1 = 0.f;
#pragma unroll
        for (int nt = 0; nt < 8; nt++) {
            float e0 = fexp2(fmaxf(fmaf(s[nt][0], L2E, -m20), -126.f));
            float e1 = fexp2(fmaxf(fmaf(s[nt][1], L2E, -m20), -126.f));
            float e2 = fexp2(fmaxf(fmaf(s[nt][2], L2E, -m21), -126.f));
            float e3 = fexp2(fmaxf(fmaf(s[nt][3], L2E, -m21), -126.f));
            rs0 += e0 + e1; rs1 += e2 + e3;
            uint2 u0 = {f2tf(e0), f2tf(e1)};
            *(uint2*)&sm->Ps[16 * w + g][8 * nt + 2 * c] = u0;
            uint2 u1 = {f2tf(e2), f2tf(e3)};
            *(uint2*)&sm->Ps[16 * w + g + 8][8 * nt + 2 * c] = u1;
        }
        rs0 += __shfl_xor_sync(~0u, rs0, 1); rs0 += __shfl_xor_sync(~0u, rs0, 2);
        rs1 += __shfl_xor_sync(~0u, rs1, 1); rs1 += __shfl_xor_sync(~0u, rs1, 2);
        l0 = l0 * a0 + rs0; l1 = l1 * a1 + rs1;
        mr0 = mn0; mr1 = mn1;
#pragma unroll
        for (int nt = 0; nt < 4; nt++) {
            o[nt][0] *= a0; o[nt][1] *= a0; o[nt][2] *= a1; o[nt][3] *= a1;
        }
        __syncwarp();
#pragma unroll
        for (int ks = 0; ks < 8; ks++) {
            unsigned pa[4] = {__float_as_uint(sm->Ps[16 * w + g][8 * ks + c]),
                              __float_as_uint(sm->Ps[16 * w + g + 8][8 * ks + c]),
                              __float_as_uint(sm->Ps[16 * w + g][8 * ks + c + 4]),
                              __float_as_uint(sm->Ps[16 * w + g + 8][8 * ks + c + 4])};
#pragma unroll
            for (int nt = 0; nt < 4; nt++)
                mma8(o[nt], pa, sm->Vs[buf][8 * ks + c][8 * nt + g],
                                sm->Vs[buf][8 * ks + c + 4][8 * nt + g]);
        }
        __syncthreads();
        buf ^= 1;
    }
    float inv0 = 1.f / l0, inv1 = 1.f / l1;
    int r0 = q0 + 16 * w + g, r1 = r0 + 8;
#pragma unroll
    for (int nt = 0; nt < 4; nt++) {
        int col = h * DD + 8 * nt + 2 * c;
        uint2 v0 = {f2tf(o[nt][0] * inv0), f2tf(o[nt][1] * inv0)};
        *(uint2*)(g_att + ((size_t)(b * SS + r0)) * CS + col) = v0;
        uint2 v1 = {f2tf(o[nt][2] * inv1), f2tf(o[nt][3] * inv1)};
        *(uint2*)(g_att + ((size_t)(b * SS + r1)) * CS + col) = v1;
    }
}

// ============================================================
// 6. out proj: cp.async double-buffered
// ============================================================
__global__ __launch_bounds__(256) void proj_mma2(const float* __restrict__ b_o,
                                                 float* __restrict__ out) {
    __shared__ unsigned As[2][128][20];
    __shared__ unsigned Bs[2][16][136];
    int tid = threadIdx.x, w = tid >> 5, lane = tid & 31, g = lane >> 2, c = lane & 3;
    int wm = w & 3, wn = w >> 2;
    int n0 = blockIdx.x * 128, m0 = blockIdx.y * 128;
    const unsigned* W = g_w[3];

    float acc0[8][4] = {}, acc1[8][4] = {};
#pragma unroll
    for (int i = 0; i < 2; i++) {
        int ch = tid * 2 + i;
        int ar = ch >> 2, ac = (ch & 3) * 4;
        cpa16(&As[0][ar][ac], g_att + (size_t)(m0 + ar) * CS + ac);
        int br = ch >> 5, bc = (ch & 31) * 4;
        cpa16(&Bs[0][br][bc], W + (size_t)br * CS + n0 + bc);
    }
    cp_commit(); cp_wait0();
    __syncthreads();

    int buf = 0;
    for (int it = 0; it < 48; it++) {
        if (it < 47) {
            int kn = (it + 1) * 16;
#pragma unroll
            for (int i = 0; i < 2; i++) {
                int ch = tid * 2 + i;
                int ar = ch >> 2, ac = (ch & 3) * 4;
                cpa16(&As[buf ^ 1][ar][ac], g_att + (size_t)(m0 + ar) * CS + kn + ac);
                int br = ch >> 5, bc = (ch & 31) * 4;
                cpa16(&Bs[buf ^ 1][br][bc], W + (size_t)(kn + br) * CS + n0 + bc);
            }
            cp_commit();
        }
#pragma unroll
        for (int ks = 0; ks < 2; ks++) {
            int r0 = wm * 32 + g;
            unsigned a0[4] = {As[buf][r0][8 * ks + c], As[buf][r0 + 8][8 * ks + c],
                              As[buf][r0][8 * ks + c + 4], As[buf][r0 + 8][8 * ks + c + 4]};
            unsigned a1[4] = {As[buf][r0 + 16][8 * ks + c], As[buf][r0 + 24][8 * ks + c],
                              As[buf][r0 + 16][8 * ks + c + 4], As[buf][r0 + 24][8 * ks + c + 4]};
#pragma unroll
            for (int nt = 0; nt < 8; nt++) {
                unsigned b0 = Bs[buf][8 * ks + c][wn * 64 + 8 * nt + g];
                unsigned b1 = Bs[buf][8 * ks + c + 4][wn * 64 + 8 * nt + g];
                mma8(acc0[nt], a0, b0, b1);
                mma8(acc1[nt], a1, b0, b1);
            }
        }
        if (it < 47) {
            cp_wait0();
            __syncthreads();
            buf ^= 1;
        }
    }

    int bi = m0 >> 10;
    const float* gate = g_emb + bi * 3 * CS + 2 * CS;
    int r0g = m0 + wm * 32 + g;
#pragma unroll
    for (int mi = 0; mi < 2; mi++) {
        float (*ac)[4] = mi ? acc1 : acc0;
        int rb = r0g + mi * 16;
#pragma unroll
        for (int nt = 0; nt < 8; nt++) {
            int col = n0 + wn * 64 + 8 * nt + 2 * c;
            float g0 = gate[col], g1 = gate[col + 1];
            float bo0 = b_o[col], bo1 = b_o[col + 1];
            float2 v0 = {(ac[nt][0] + bo0) * g0, (ac[nt][1] + bo1) * g1};
            *(float2*)(out + (size_t)rb * CS + col) = v0;
            float2 v1 = {(ac[nt][2] + bo0) * g0, (ac[nt][3] + bo1) * g1};
            *(float2*)(out + (size_t)(rb + 8) * CS + col) = v1;
        }
    }
}

// ============================================================
extern "C" void kernel_launch(void* const* d_in, const int* in_sizes, int n_in,
                              void* d_out, int out_size) {
    const float* bs      = (const float*)d_in[0];
    const float* z       = (const float*)d_in[1];
    const float* t       = (const float*)d_in[2];
    const float* beta    = (const float*)d_in[3];
    const int*   z_mask  = (const int*)  d_in[4];
    const float* w_adaln = (const float*)d_in[5];
    const float* b_adaln = (const float*)d_in[6];
    const float* ln_z_w  = (const float*)d_in[7];
    const float* ln_z_b  = (const float*)d_in[8];
    const float* w_q     = (const float*)d_in[9];
    const float* w_k     = (const float*)d_in[10];
    const float* w_v     = (const float*)d_in[11];
    const float* w_z     = (const float*)d_in[12];
    const float* rms_q_w = (const float*)d_in[13];
    const float* rms_k_w = (const float*)d_in[14];
    const float* w_o     = (const float*)d_in[15];
    const float* b_o     = (const float*)d_in[16];
    float* out = (float*)d_out;

    static const int ATTN_SMEM = (int)sizeof(AttnSmem);
    cudaFuncSetAttribute(attn_mma, cudaFuncAttributeMaxDynamicSharedMemorySize, ATTN_SMEM);

    adaln_kernel<<<dim3(9, 2), 256>>>(t, w_adaln, b_adaln);
    wconv_kernel<<<576, 256>>>(w_q, w_k, w_v, w_o);
    bsnorm_kernel<<<NB * SS, 256>>>(bs);
    bias_mma<<<dim3(16, SS), 128>>>(z, z_mask, ln_z_w, ln_z_b, w_z);
    qkv_mma2<<<dim3(18, 16), 256>>>(rms_q_w, rms_k_w);
    attn_mma<<<dim3(8, NH, NB), 256, ATTN_SMEM>>>(beta);
    proj_mma2<<<dim3(6, 16), 256>>>(b_o, out);
}

// round 6
// speedup vs baseline: 1.5705x; 1.0112x over previous
#include <cuda_runtime.h>
#include <math.h>
#include <stdint.h>

#define SS 1024
#define CS 768
#define CZ 128
#define NH 24
#define DD 32
#define NB 2
#define L2E 1.4426950408889634f

// ---- scratch ----
__device__ float    g_emb[NB * 3 * CS];
__device__ unsigned g_bsn[NB * SS * CS];                 // tf32 bits
__device__ unsigned g_qkv[3 * NB * NH * SS * DD];        // tf32 bits (q pre-scaled, rms folded)
__device__ float    g_bias[(size_t)NH * SS * SS];        // (h,i,j) fp32
__device__ unsigned g_att[NB * SS * CS];                 // tf32 bits
__device__ unsigned g_w[4][CS * CS];                     // tf32 wq,wk,wv,wo
__device__ unsigned g_wtp[NH * CZ];                      // tf32 lnw*wz, [n][k]
__device__ float    g_ah[NH], g_bh[NH];

__device__ __forceinline__ unsigned f2tf(float x) {
    unsigned u; asm("cvt.rna.tf32.f32 %0, %1;" : "=r"(u) : "f"(x)); return u;
}
__device__ __forceinline__ void mma8(float* c, const unsigned* a, unsigned b0, unsigned b1) {
    asm volatile("mma.sync.aligned.m16n8k8.row.col.f32.tf32.tf32.f32 "
        "{%0,%1,%2,%3},{%4,%5,%6,%7},{%8,%9},{%0,%1,%2,%3};"
        : "+f"(c[0]), "+f"(c[1]), "+f"(c[2]), "+f"(c[3])
        : "r"(a[0]), "r"(a[1]), "r"(a[2]), "r"(a[3]), "r"(b0), "r"(b1));
}
__device__ __forceinline__ void cpa16(void* s, const void* g) {
    asm volatile("cp.async.cg.shared.global [%0], [%1], 16;"
                 :: "r"((unsigned)__cvta_generic_to_shared(s)), "l"(g));
}
__device__ __forceinline__ void cp_commit() { asm volatile("cp.async.commit_group;"); }
__device__ __forceinline__ void cp_wait0()  { asm volatile("cp.async.wait_group 0;"); }
__device__ __forceinline__ void cp_wait1()  { asm volatile("cp.async.wait_group 1;"); }

// fast 2^y on fma pipe; caller clamps y >= -126
__device__ __forceinline__ float fexp2(float y) {
    float t = y + 12582912.f;
    int ei = __float_as_int(t) << 23;
    float f = y - (t - 12582912.f);
    float p = 0.0013333558f;
    p = fmaf(p, f, 0.0096181291f);
    p = fmaf(p, f, 0.0555041087f);
    p = fmaf(p, f, 0.2402265069f);
    p = fmaf(p, f, 0.6931471806f);
    p = fmaf(p, f, 1.f);
    return __int_as_float(__float_as_int(p) + ei);
}

// ============================================================
// 0a. weight pre-convert to tf32
// ============================================================
__global__ void wconv_kernel(const float* __restrict__ wq, const float* __restrict__ wk,
                             const float* __restrict__ wv, const float* __restrict__ wo) {
    int i4 = (blockIdx.x * 256 + threadIdx.x) * 4;
    if (i4 >= CS * CS) return;
    const float* src[4] = {wq, wk, wv, wo};
#pragma unroll
    for (int a = 0; a < 4; a++) {
        float4 v = *(const float4*)(src[a] + i4);
        uint4 u = {f2tf(v.x), f2tf(v.y), f2tf(v.z), f2tf(v.w)};
        *(uint4*)&g_w[a][i4] = u;
    }
}

// ============================================================
// 0b. bias prep: WT = tf32(lnw*wz) [n][k], Ah, Bh  (one block)
// ============================================================
__global__ void bprep_kernel(const float* __restrict__ lnw, const float* __restrict__ lnb,
                             const float* __restrict__ wz) {
    int tid = threadIdx.x;
    for (int idx = tid; idx < NH * CZ; idx += 256) {
        int n = idx >> 7, k = idx & 127;
        g_wtp[idx] = f2tf(lnw[k] * wz[k * NH + n]);
    }
    if (tid < NH) {
        float a = 0.f, bb = 0.f;
        for (int k = 0; k < CZ; k++) {
            float wv = wz[k * NH + tid];
            a += lnw[k] * wv; bb += lnb[k] * wv;
        }
        g_ah[tid] = a; g_bh[tid] = bb;
    }
}

// ============================================================
// 1. adaLN
// ============================================================
__global__ void adaln_kernel(const float* __restrict__ t,
                             const float* __restrict__ w,
                             const float* __restrict__ bb) {
    int b = blockIdx.y;
    int n = blockIdx.x * 256 + threadIdx.x;
    __shared__ float st[CS];
    for (int c = threadIdx.x; c < CS; c += 256) {
        float v = t[b * CS + c];
        st[c] = v / (1.f + __expf(-v));
    }
    __syncthreads();
    float acc = bb[n];
#pragma unroll 4
    for (int c = 0; c < CS; c++) acc = fmaf(st[c], w[c * (3 * CS) + n], acc);
    g_emb[b * 3 * CS + n] = acc;
}

// ============================================================
// 2. bs LayerNorm + adaLN modulate -> tf32 g_bsn
// ============================================================
__global__ void bsnorm_kernel(const float* __restrict__ bs) {
    int row = blockIdx.x;
    int b = row >> 10;
    const float* x = bs + (size_t)row * CS;
    int tid = threadIdx.x;
    float v0 = x[tid], v1 = x[tid + 256], v2 = x[tid + 512];

    __shared__ float red1[8], red2[8];
    float s = v0 + v1 + v2;
    for (int o = 16; o; o >>= 1) s += __shfl_xor_sync(~0u, s, o);
    if ((tid & 31) == 0) red1[tid >> 5] = s;
    __syncthreads();
    float tot = 0.f;
#pragma unroll
    for (int i = 0; i < 8; i++) tot += red1[i];
    float mu = tot * (1.f / CS);

    float d0 = v0 - mu, d1 = v1 - mu, d2 = v2 - mu;
    float q = d0 * d0 + d1 * d1 + d2 * d2;
    for (int o = 16; o; o >>= 1) q += __shfl_xor_sync(~0u, q, o);
    if ((tid & 31) == 0) red2[tid >> 5] = q;
    __syncthreads();
    float tot2 = 0.f;
#pragma unroll
    for (int i = 0; i < 8; i++) tot2 += red2[i];
    float rsig = rsqrtf(tot2 * (1.f / CS) + 1e-5f);

    const float* e = g_emb + b * 3 * CS;
    unsigned* outp = g_bsn + (size_t)row * CS;
    outp[tid]       = f2tf(d0 * rsig * (1.f + e[CS + tid])       + e[tid]);
    outp[tid + 256] = f2tf(d1 * rsig * (1.f + e[CS + tid + 256]) + e[tid + 256]);
    outp[tid + 512] = f2tf(d2 * rsig * (1.f + e[CS + tid + 512]) + e[tid + 512]);
}

// ============================================================
// 3. QKV GEMM, cp.async double-buffered, fused RMS + q-scale
// ============================================================
__global__ __launch_bounds__(256) void qkv_mma2(const float* __restrict__ rqw,
                                                const float* __restrict__ rkw) {
    __shared__ unsigned As[2][128][20];
    __shared__ unsigned Bs[2][16][136];
    int tid = threadIdx.x, w = tid >> 5, lane = tid & 31, g = lane >> 2, c = lane & 3;
    int wm = w & 3, wn = w >> 2;
    int n0 = blockIdx.x * 128;
    int sel = n0 / CS, nc = n0 - sel * CS;
    const unsigned* W = g_w[sel];
    int m0 = blockIdx.y * 128;

    float acc0[8][4] = {}, acc1[8][4] = {};
#pragma unroll
    for (int i = 0; i < 2; i++) {
        int ch = tid * 2 + i;
        int ar = ch >> 2, ac = (ch & 3) * 4;
        cpa16(&As[0][ar][ac], g_bsn + (size_t)(m0 + ar) * CS + ac);
        int br = ch >> 5, bc = (ch & 31) * 4;
        cpa16(&Bs[0][br][bc], W + (size_t)br * CS + nc + bc);
    }
    cp_commit(); cp_wait0();
    __syncthreads();

    int buf = 0;
    for (int it = 0; it < 48; it++) {
        if (it < 47) {
            int kn = (it + 1) * 16;
#pragma unroll
            for (int i = 0; i < 2; i++) {
                int ch = tid * 2 + i;
                int ar = ch >> 2, ac = (ch & 3) * 4;
                cpa16(&As[buf ^ 1][ar][ac], g_bsn + (size_t)(m0 + ar) * CS + kn + ac);
                int br = ch >> 5, bc = (ch & 31) * 4;
                cpa16(&Bs[buf ^ 1][br][bc], W + (size_t)(kn + br) * CS + nc + bc);
            }
            cp_commit();
        }
#pragma unroll
        for (int ks = 0; ks < 2; ks++) {
            int r0 = wm * 32 + g;
            unsigned a0[4] = {As[buf][r0][8 * ks + c], As[buf][r0 + 8][8 * ks + c],
                              As[buf][r0][8 * ks + c + 4], As[buf][r0 + 8][8 * ks + c + 4]};
            unsigned a1[4] = {As[buf][r0 + 16][8 * ks + c], As[buf][r0 + 24][8 * ks + c],
                              As[buf][r0 + 16][8 * ks + c + 4], As[buf][r0 + 24][8 * ks + c + 4]};
#pragma unroll
            for (int nt = 0; nt < 8; nt++) {
                unsigned b0 = Bs[buf][8 * ks + c][wn * 64 + 8 * nt + g];
                unsigned b1 = Bs[buf][8 * ks + c + 4][wn * 64 + 8 * nt + g];
                mma8(acc0[nt], a0, b0, b1);
                mma8(acc1[nt], a1, b0, b1);
            }
        }
        if (it < 47) {
            cp_wait0();
            __syncthreads();
            buf ^= 1;
        }
    }

    const float SC = 0.17677669529663687f;
    int bi = m0 >> 10;
    int r0g = m0 + wm * 32 + g;
#pragma unroll
    for (int mi = 0; mi < 2; mi++) {
        float (*ac)[4] = mi ? acc1 : acc0;
        int rb = r0g + mi * 16;
        int s0 = rb & 1023, s1 = s0 + 8;
#pragma unroll
        for (int hf = 0; hf < 2; hf++) {
            int h = (nc + wn * 64 + hf * 32) >> 5;
            float ss0 = 0.f, ss1 = 0.f;
#pragma unroll
            for (int nt = hf * 4; nt < hf * 4 + 4; nt++) {
                ss0 += ac[nt][0] * ac[nt][0] + ac[nt][1] * ac[nt][1];
                ss1 += ac[nt][2] * ac[nt][2] + ac[nt][3] * ac[nt][3];
            }
            float rs0 = 1.f, rs1 = 1.f;
            if (sel < 2) {
                ss0 += __shfl_xor_sync(~0u, ss0, 1); ss0 += __shfl_xor_sync(~0u, ss0, 2);
                ss1 += __shfl_xor_sync(~0u, ss1, 1); ss1 += __shfl_xor_sync(~0u, ss1, 2);
                rs0 = rsqrtf(ss0 * (1.f / 32) + 1e-5f);
                rs1 = rsqrtf(ss1 * (1.f / 32) + 1e-5f);
                if (sel == 0) { rs0 *= SC; rs1 *= SC; }
            }
            unsigned* basep = g_qkv + ((size_t)(sel * NB + bi) * NH + h) * SS * DD;
            const float* wr = (sel == 0) ? rqw : rkw;
#pragma unroll
            for (int nt = hf * 4; nt < hf * 4 + 4; nt++) {
                int d = (8 * nt + 2 * c) & 31;
                float w0 = 1.f, w1 = 1.f;
                if (sel < 2) { w0 = wr[d]; w1 = wr[d + 1]; }
                unsigned* p0 = basep + (size_t)s0 * DD + d;
                p0[0] = f2tf(ac[nt][0] * rs0 * w0); p0[1] = f2tf(ac[nt][1] * rs0 * w1);
                unsigned* p1 = basep + (size_t)s1 * DD + d;
                p1[0] = f2tf(ac[nt][2] * rs1 * w0); p1[1] = f2tf(ac[nt][3] * rs1 * w1);
            }
        }
    }
}

// ============================================================
// 4. bias via tf32 mma, j-tile 128, precomputed WT/Ah/Bh,
//    raw-bit z staging (no cvt)
// ============================================================
struct BiasSmem {
    unsigned Zs[128][132];
    unsigned WT[24][132];
    float muS[128], rsS[128];
    float AhS[24], BhS[24];
    int mS[128];
};

__global__ __launch_bounds__(256) void bias_mma2(const float* __restrict__ z,
                                                 const int* __restrict__ zmask) {
    extern __shared__ char smem_raw[];
    BiasSmem* sm = (BiasSmem*)smem_raw;
    int i = blockIdx.y, jt = blockIdx.x * 128;
    int tid = threadIdx.x, w = tid >> 5, lane = tid & 31, g = lane >> 2, c = lane & 3;

    for (int idx = tid; idx < NH * CZ; idx += 256) {
        int n = idx >> 7, k = idx & 127;
        sm->WT[n][k] = g_wtp[idx];
    }
    if (tid < NH) { sm->AhS[tid] = g_ah[tid]; sm->BhS[tid] = g_bh[tid]; }
    if (tid < 128) sm->mS[tid] = zmask[(size_t)i * SS + jt + tid];
    __syncthreads();

    // z staging (raw fp32 bits) + LN stats; half-row per thread
    {
        int r = tid >> 1, hh = tid & 1;
        bool live = sm->mS[r] != 0;
        const float4* zr = (const float4*)(z + ((size_t)i * SS + jt + r) * CZ + hh * 64);
        float s = 0.f, q = 0.f;
#pragma unroll
        for (int t = 0; t < 16; t++) {
            float4 v = live ? zr[t] : make_float4(0.f, 0.f, 0.f, 0.f);
            s += v.x + v.y + v.z + v.w;
            q += v.x * v.x + v.y * v.y + v.z * v.z + v.w * v.w;
            *(float4*)&sm->Zs[r][hh * 64 + t * 4] = v;
        }
        s += __shfl_xor_sync(~0u, s, 1);
        q += __shfl_xor_sync(~0u, q, 1);
        if (hh == 0) {
            float mu = s * (1.f / CZ);
            float var = q * (1.f / CZ) - mu * mu;
            sm->muS[r] = mu;
            sm->rsS[r] = rsqrtf(var + 1e-5f);
        }
    }
    __syncthreads();

    float acc[3][4] = {};
#pragma unroll
    for (int ks = 0; ks < 16; ks++) {
        unsigned a[4] = {sm->Zs[16 * w + g][8 * ks + c], sm->Zs[16 * w + g + 8][8 * ks + c],
                         sm->Zs[16 * w + g][8 * ks + c + 4], sm->Zs[16 * w + g + 8][8 * ks + c + 4]};
#pragma unroll
        for (int nt = 0; nt < 3; nt++)
            mma8(acc[nt], a, sm->WT[8 * nt + g][8 * ks + c], sm->WT[8 * nt + g][8 * ks + c + 4]);
    }

    int j0 = 16 * w + g, j1 = j0 + 8;
    float mu0 = sm->muS[j0], rg0 = sm->rsS[j0], mu1 = sm->muS[j1], rg1 = sm->rsS[j1];
    bool k0m = sm->mS[j0] != 0, k1m = sm->mS[j1] != 0;
#pragma unroll
    for (int nt = 0; nt < 3; nt++) {
        int h = 8 * nt + 2 * c;
        float A0 = sm->AhS[h], B0 = sm->BhS[h], A1 = sm->AhS[h + 1], B1 = sm->BhS[h + 1];
        size_t b0 = ((size_t)h * SS + i) * SS + jt;
        size_t b1 = ((size_t)(h + 1) * SS + i) * SS + jt;
        g_bias[b0 + j0] = k0m ? rg0 * (acc[nt][0] - mu0 * A0) + B0 : -1e9f;
        g_bias[b1 + j0] = k0m ? rg0 * (acc[nt][1] - mu0 * A1) + B1 : -1e9f;
        g_bias[b0 + j1] = k1m ? rg1 * (acc[nt][2] - mu1 * A0) + B0 : -1e9f;
        g_bias[b1 + j1] = k1m ? rg1 * (acc[nt][3] - mu1 * A1) + B1 : -1e9f;
    }
}

// ============================================================
// 5. flash attention (P stored as raw bits, no cvt)
// ============================================================
struct AttnSmem {
    unsigned Qs[128][36];
    unsigned Ks[2][64][36];
    unsigned Vs[2][64][40];
    float    Ps[128][68];
};

__global__ __launch_bounds__(256) void attn_mma(const float* __restrict__ beta) {
    extern __shared__ char smem_raw[];
    AttnSmem* sm = (AttnSmem*)smem_raw;
    int b = blockIdx.z, h = blockIdx.y, q0 = blockIdx.x * 128;
    int tid = threadIdx.x, w = tid >> 5, lane = tid & 31, g = lane >> 2, c = lane & 3;

    const unsigned* qptr = g_qkv + ((size_t)(0 * NB + b) * NH + h) * SS * DD;
    const unsigned* kptr = g_qkv + ((size_t)(1 * NB + b) * NH + h) * SS * DD;
    const unsigned* vptr = g_qkv + ((size_t)(2 * NB + b) * NH + h) * SS * DD;
    const float* zp = g_bias + ((size_t)h * SS + q0) * SS;
    const float* bp = beta + ((size_t)b * SS + q0) * SS;

#pragma unroll
    for (int i = 0; i < 4; i++) {
        int ch = tid + 256 * i;
        int r = ch >> 3, col = (ch & 7) * 4;
        cpa16(&sm->Qs[r][col], qptr + (size_t)(q0 + r) * DD + col);
    }
#pragma unroll
    for (int i = 0; i < 2; i++) {
        int ch = tid + 256 * i;
        int r = ch >> 3, col = (ch & 7) * 4;
        cpa16(&sm->Ks[0][r][col], kptr + (size_t)r * DD + col);
        cpa16(&sm->Vs[0][r][col], vptr + (size_t)r * DD + col);
    }
    cp_commit(); cp_wait0();
    __syncthreads();

    unsigned qa[4][4];
#pragma unroll
    for (int ks = 0; ks < 4; ks++) {
        qa[ks][0] = sm->Qs[16 * w + g][8 * ks + c];
        qa[ks][1] = sm->Qs[16 * w + g + 8][8 * ks + c];
        qa[ks][2] = sm->Qs[16 * w + g][8 * ks + c + 4];
        qa[ks][3] = sm->Qs[16 * w + g + 8][8 * ks + c + 4];
    }
    float mr0 = -1e30f, mr1 = -1e30f, l0 = 0.f, l1 = 0.f;
    float o[4][4] = {};

    int buf = 0;
    for (int kt = 0; kt < 16; kt++) {
        int k0 = kt * 64;
        if (kt < 15) {
            int kn = k0 + 64;
#pragma unroll
            for (int i = 0; i < 2; i++) {
                int ch = tid + 256 * i;
                int r = ch >> 3, col = (ch & 7) * 4;
                cpa16(&sm->Ks[buf ^ 1][r][col], kptr + (size_t)(kn + r) * DD + col);
                cpa16(&sm->Vs[buf ^ 1][r][col], vptr + (size_t)(kn + r) * DD + col);
            }
            cp_commit();
        }
        for (int idx = tid; idx < 2048; idx += 256) {
            int r = idx >> 4, c4 = (idx & 15) * 4;
            float4 zb = *(const float4*)(zp + (size_t)r * SS + k0 + c4);
            float4 bt = *(const float4*)(bp + (size_t)r * SS + k0 + c4);
            zb.x += bt.x; zb.y += bt.y; zb.z += bt.z; zb.w += bt.w;
            *(float4*)&sm->Ps[r][c4] = zb;
        }
        if (kt < 15) cp_wait1(); else cp_wait0();
        __syncthreads();

        float s[8][4] = {};
#pragma unroll
        for (int ks = 0; ks < 4; ks++) {
#pragma unroll
            for (int nt = 0; nt < 8; nt++)
                mma8(s[nt], qa[ks], sm->Ks[buf][8 * nt + g][8 * ks + c],
                                    sm->Ks[buf][8 * nt + g][8 * ks + c + 4]);
        }
        float mx0 = -1e30f, mx1 = -1e30f;
#pragma unroll
        for (int nt = 0; nt < 8; nt++) {
            s[nt][0] += sm->Ps[16 * w + g][8 * nt + 2 * c];
            s[nt][1] += sm->Ps[16 * w + g][8 * nt + 2 * c + 1];
            s[nt][2] += sm->Ps[16 * w + g + 8][8 * nt + 2 * c];
            s[nt][3] += sm->Ps[16 * w + g + 8][8 * nt + 2 * c + 1];
            mx0 = fmaxf(mx0, fmaxf(s[nt][0], s[nt][1]));
            mx1 = fmaxf(mx1, fmaxf(s[nt][2], s[nt][3]));
        }
        mx0 = fmaxf(mx0, __shfl_xor_sync(~0u, mx0, 1));
        mx0 = fmaxf(mx0, __shfl_xor_sync(~0u, mx0, 2));
        mx1 = fmaxf(mx1, __shfl_xor_sync(~0u, mx1, 1));
        mx1 = fmaxf(mx1, __shfl_xor_sync(~0u, mx1, 2));
        float mn0 = fmaxf(mr0, mx0), mn1 = fmaxf(mr1, mx1);
        float a0 = fexp2(fmaxf((mr0 - mn0) * L2E, -126.f));
        float a1 = fexp2(fmaxf((mr1 - mn1) * L2E, -126.f));
        float m20 = mn0 * L2E, m21 = mn1 * L2E;
        float rs0 = 0.f, rs1 = 0.f;
#pragma unroll
        for (int nt = 0; nt < 8; nt++) {
            float e0 = fexp2(fmaxf(fmaf(s[nt][0], L2E, -m20), -126.f));
            float e1 = fexp2(fmaxf(fmaf(s[nt][1], L2E, -m20), -126.f));
            float e2 = fexp2(fmaxf(fmaf(s[nt][2], L2E, -m21), -126.f));
            float e3 = fexp2(fmaxf(fmaf(s[nt][3], L2E, -m21), -126.f));
            rs0 += e0 + e1; rs1 += e2 + e3;
            float2 f0 = {e0, e1};
            *(float2*)&sm->Ps[16 * w + g][8 * nt + 2 * c] = f0;
            float2 f1 = {e2, e3};
            *(float2*)&sm->Ps[16 * w + g + 8][8 * nt + 2 * c] = f1;
        }
        rs0 += __shfl_xor_sync(~0u, rs0, 1); rs0 += __shfl_xor_sync(~0u, rs0, 2);
        rs1 += __shfl_xor_sync(~0u, rs1, 1); rs1 += __shfl_xor_sync(~0u, rs1, 2);
        l0 = l0 * a0 + rs0; l1 = l1 * a1 + rs1;
        mr0 = mn0; mr1 = mn1;
#pragma unroll
        for (int nt = 0; nt < 4; nt++) {
            o[nt][0] *= a0; o[nt][1] *= a0; o[nt][2] *= a1; o[nt][3] *= a1;
        }
        __syncwarp();
#pragma unroll
        for (int ks = 0; ks < 8; ks++) {
            unsigned pa[4] = {__float_as_uint(sm->Ps[16 * w + g][8 * ks + c]),
                              __float_as_uint(sm->Ps[16 * w + g + 8][8 * ks + c]),
                              __float_as_uint(sm->Ps[16 * w + g][8 * ks + c + 4]),
                              __float_as_uint(sm->Ps[16 * w + g + 8][8 * ks + c + 4])};
#pragma unroll
            for (int nt = 0; nt < 4; nt++)
                mma8(o[nt], pa, sm->Vs[buf][8 * ks + c][8 * nt + g],
                                sm->Vs[buf][8 * ks + c + 4][8 * nt + g]);
        }
        __syncthreads();
        buf ^= 1;
    }
    float inv0 = 1.f / l0, inv1 = 1.f / l1;
    int r0 = q0 + 16 * w + g, r1 = r0 + 8;
#pragma unroll
    for (int nt = 0; nt < 4; nt++) {
        int col = h * DD + 8 * nt + 2 * c;
        uint2 v0 = {f2tf(o[nt][0] * inv0), f2tf(o[nt][1] * inv0)};
        *(uint2*)(g_att + ((size_t)(b * SS + r0)) * CS + col) = v0;
        uint2 v1 = {f2tf(o[nt][2] * inv1), f2tf(o[nt][3] * inv1)};
        *(uint2*)(g_att + ((size_t)(b * SS + r1)) * CS + col) = v1;
    }
}

// ============================================================
// 6. out proj: cp.async double-buffered
// ============================================================
__global__ __launch_bounds__(256) void proj_mma2(const float* __restrict__ b_o,
                                                 float* __restrict__ out) {
    __shared__ unsigned As[2][128][20];
    __shared__ unsigned Bs[2][16][136];
    int tid = threadIdx.x, w = tid >> 5, lane = tid & 31, g = lane >> 2, c = lane & 3;
    int wm = w & 3, wn = w >> 2;
    int n0 = blockIdx.x * 128, m0 = blockIdx.y * 128;
    const unsigned* W = g_w[3];

    float acc0[8][4] = {}, acc1[8][4] = {};
#pragma unroll
    for (int i = 0; i < 2; i++) {
        int ch = tid * 2 + i;
        int ar = ch >> 2, ac = (ch & 3) * 4;
        cpa16(&As[0][ar][ac], g_att + (size_t)(m0 + ar) * CS + ac);
        int br = ch >> 5, bc = (ch & 31) * 4;
        cpa16(&Bs[0][br][bc], W + (size_t)br * CS + n0 + bc);
    }
    cp_commit(); cp_wait0();
    __syncthreads();

    int buf = 0;
    for (int it = 0; it < 48; it++) {
        if (it < 47) {
            int kn = (it + 1) * 16;
#pragma unroll
            for (int i = 0; i < 2; i++) {
                int ch = tid * 2 + i;
                int ar = ch >> 2, ac = (ch & 3) * 4;
                cpa16(&As[buf ^ 1][ar][ac], g_att + (size_t)(m0 + ar) * CS + kn + ac);
                int br = ch >> 5, bc = (ch & 31) * 4;
                cpa16(&Bs[buf ^ 1][br][bc], W + (size_t)(kn + br) * CS + n0 + bc);
            }
            cp_commit();
        }
#pragma unroll
        for (int ks = 0; ks < 2; ks++) {
            int r0 = wm * 32 + g;
            unsigned a0[4] = {As[buf][r0][8 * ks + c], As[buf][r0 + 8][8 * ks + c],
                              As[buf][r0][8 * ks + c + 4], As[buf][r0 + 8][8 * ks + c + 4]};
            unsigned a1[4] = {As[buf][r0 + 16][8 * ks + c], As[buf][r0 + 24][8 * ks + c],
                              As[buf][r0 + 16][8 * ks + c + 4], As[buf][r0 + 24][8 * ks + c + 4]};
#pragma unroll
            for (int nt = 0; nt < 8; nt++) {
                unsigned b0 = Bs[buf][8 * ks + c][wn * 64 + 8 * nt + g];
                unsigned b1 = Bs[buf][8 * ks + c + 4][wn * 64 + 8 * nt + g];
                mma8(acc0[nt], a0, b0, b1);
                mma8(acc1[nt], a1, b0, b1);
            }
        }
        if (it < 47) {
            cp_wait0();
            __syncthreads();
            buf ^= 1;
        }
    }

    int bi = m0 >> 10;
    const float* gate = g_emb + bi * 3 * CS + 2 * CS;
    int r0g = m0 + wm * 32 + g;
#pragma unroll
    for (int mi = 0; mi < 2; mi++) {
        float (*ac)[4] = mi ? acc1 : acc0;
        int rb = r0g + mi * 16;
#pragma unroll
        for (int nt = 0; nt < 8; nt++) {
            int col = n0 + wn * 64 + 8 * nt + 2 * c;
            float g0 = gate[col], g1 = gate[col + 1];
            float bo0 = b_o[col], bo1 = b_o[col + 1];
            float2 v0 = {(ac[nt][0] + bo0) * g0, (ac[nt][1] + bo1) * g1};
            *(float2*)(out + (size_t)rb * CS + col) = v0;
            float2 v1 = {(ac[nt][2] + bo0) * g0, (ac[nt][3] + bo1) * g1};
            *(float2*)(out + (size_t)(rb + 8) * CS + col) = v1;
        }
    }
}

// ============================================================
extern "C" void kernel_launch(void* const* d_in, const int* in_sizes, int n_in,
                              void* d_out, int out_size) {
    const float* bs      = (const float*)d_in[0];
    const float* z       = (const float*)d_in[1];
    const float* t       = (const float*)d_in[2];
    const float* beta    = (const float*)d_in[3];
    const int*   z_mask  = (const int*)  d_in[4];
    const float* w_adaln = (const float*)d_in[5];
    const float* b_adaln = (const float*)d_in[6];
    const float* ln_z_w  = (const float*)d_in[7];
    const float* ln_z_b  = (const float*)d_in[8];
    const float* w_q     = (const float*)d_in[9];
    const float* w_k     = (const float*)d_in[10];
    const float* w_v     = (const float*)d_in[11];
    const float* w_z     = (const float*)d_in[12];
    const float* rms_q_w = (const float*)d_in[13];
    const float* rms_k_w = (const float*)d_in[14];
    const float* w_o     = (const float*)d_in[15];
    const float* b_o     = (const float*)d_in[16];
    float* out = (float*)d_out;

    static const int ATTN_SMEM = (int)sizeof(AttnSmem);
    static const int BIAS_SMEM = (int)sizeof(BiasSmem);
    cudaFuncSetAttribute(attn_mma, cudaFuncAttributeMaxDynamicSharedMemorySize, ATTN_SMEM);
    cudaFuncSetAttribute(bias_mma2, cudaFuncAttributeMaxDynamicSharedMemorySize, BIAS_SMEM);

    adaln_kernel<<<dim3(9, 2), 256>>>(t, w_adaln, b_adaln);
    wconv_kernel<<<576, 256>>>(w_q, w_k, w_v, w_o);
    bprep_kernel<<<1, 256>>>(ln_z_w, ln_z_b, w_z);
    bsnorm_kernel<<<NB * SS, 256>>>(bs);
    bias_mma2<<<dim3(8, SS), 256, BIAS_SMEM>>>(z, z_mask);
    qkv_mma2<<<dim3(18, 16), 256>>>(rms_q_w, rms_k_w);
    attn_mma<<<dim3(8, NH, NB), 256, ATTN_SMEM>>>(beta);
    proj_mma2<<<dim3(6, 16), 256>>>(b_o, out);
}

// round 9
// speedup vs baseline: 1.5863x; 1.0101x over previous
#include <cuda_runtime.h>
#include <math.h>
#include <stdint.h>

#define SS 1024
#define CS 768
#define CZ 128
#define NH 24
#define DD 32
#define NB 2
#define L2E 1.4426950408889634f

// ---- scratch ----
__device__ float    g_emb[NB * 3 * CS];
__device__ unsigned g_bsn[NB * SS * CS];                 // tf32 bits
__device__ unsigned g_qkv[3 * NB * NH * SS * DD];        // tf32 bits (q pre-scaled, rms folded)
__device__ float    g_bias[(size_t)NB * NH * SS * SS];   // (b,h,i,j) fp32, beta folded
__device__ unsigned g_att[NB * SS * CS];                 // tf32 bits
__device__ unsigned g_w[4][CS * CS];                     // tf32 wq,wk,wv,wo
__device__ unsigned g_wtp[NH * CZ];                      // tf32 lnw*wz, [n][k]
__device__ float    g_ah[NH], g_bh[NH];

__device__ __forceinline__ unsigned f2tf(float x) {
    unsigned u; asm("cvt.rna.tf32.f32 %0, %1;" : "=r"(u) : "f"(x)); return u;
}
__device__ __forceinline__ void mma8(float* c, const unsigned* a, unsigned b0, unsigned b1) {
    asm volatile("mma.sync.aligned.m16n8k8.row.col.f32.tf32.tf32.f32 "
        "{%0,%1,%2,%3},{%4,%5,%6,%7},{%8,%9},{%0,%1,%2,%3};"
        : "+f"(c[0]), "+f"(c[1]), "+f"(c[2]), "+f"(c[3])
        : "r"(a[0]), "r"(a[1]), "r"(a[2]), "r"(a[3]), "r"(b0), "r"(b1));
}
__device__ __forceinline__ void cpa16(void* s, const void* g) {
    asm volatile("cp.async.cg.shared.global [%0], [%1], 16;"
                 :: "r"((unsigned)__cvta_generic_to_shared(s)), "l"(g));
}
__device__ __forceinline__ void cp_commit() { asm volatile("cp.async.commit_group;"); }
__device__ __forceinline__ void cp_wait0()  { asm volatile("cp.async.wait_group 0;"); }

// fast 2^y on fma pipe; caller clamps y >= -126
__device__ __forceinline__ float fexp2(float y) {
    float t = y + 12582912.f;
    int ei = __float_as_int(t) << 23;
    float f = y - (t - 12582912.f);
    float p = 0.0013333558f;
    p = fmaf(p, f, 0.0096181291f);
    p = fmaf(p, f, 0.0555041087f);
    p = fmaf(p, f, 0.2402265069f);
    p = fmaf(p, f, 0.6931471806f);
    p = fmaf(p, f, 1.f);
    return __int_as_float(__float_as_int(p) + ei);
}

// ============================================================
// 0a. weight pre-convert to tf32
// ============================================================
__global__ void wconv_kernel(const float* __restrict__ wq, const float* __restrict__ wk,
                             const float* __restrict__ wv, const float* __restrict__ wo) {
    int i4 = (blockIdx.x * 256 + threadIdx.x) * 4;
    if (i4 >= CS * CS) return;
    const float* src[4] = {wq, wk, wv, wo};
#pragma unroll
    for (int a = 0; a < 4; a++) {
        float4 v = *(const float4*)(src[a] + i4);
        uint4 u = {f2tf(v.x), f2tf(v.y), f2tf(v.z), f2tf(v.w)};
        *(uint4*)&g_w[a][i4] = u;
    }
}

// ============================================================
// 0b. bias prep: WT = tf32(lnw*wz) [n][k], Ah, Bh  (one block)
// ============================================================
__global__ void bprep_kernel(const float* __restrict__ lnw, const float* __restrict__ lnb,
                             const float* __restrict__ wz) {
    int tid = threadIdx.x;
    for (int idx = tid; idx < NH * CZ; idx += 256) {
        int n = idx >> 7, k = idx & 127;
        g_wtp[idx] = f2tf(lnw[k] * wz[k * NH + n]);
    }
    if (tid < NH) {
        float a = 0.f, bb = 0.f;
        for (int k = 0; k < CZ; k++) {
            float wv = wz[k * NH + tid];
            a += lnw[k] * wv; bb += lnb[k] * wv;
        }
        g_ah[tid] = a; g_bh[tid] = bb;
    }
}

// ============================================================
// 1. adaLN
// ============================================================
__global__ void adaln_kernel(const float* __restrict__ t,
                             const float* __restrict__ w,
                             const float* __restrict__ bb) {
    int b = blockIdx.y;
    int n = blockIdx.x * 256 + threadIdx.x;
    __shared__ float st[CS];
    for (int c = threadIdx.x; c < CS; c += 256) {
        float v = t[b * CS + c];
        st[c] = v / (1.f + __expf(-v));
    }
    __syncthreads();
    float acc = bb[n];
#pragma unroll 4
    for (int c = 0; c < CS; c++) acc = fmaf(st[c], w[c * (3 * CS) + n], acc);
    g_emb[b * 3 * CS + n] = acc;
}

// ============================================================
// 2. bs LayerNorm + adaLN modulate -> tf32 g_bsn
// ============================================================
__global__ void bsnorm_kernel(const float* __restrict__ bs) {
    int row = blockIdx.x;
    int b = row >> 10;
    const float* x = bs + (size_t)row * CS;
    int tid = threadIdx.x;
    float v0 = x[tid], v1 = x[tid + 256], v2 = x[tid + 512];

    __shared__ float red1[8], red2[8];
    float s = v0 + v1 + v2;
    for (int o = 16; o; o >>= 1) s += __shfl_xor_sync(~0u, s, o);
    if ((tid & 31) == 0) red1[tid >> 5] = s;
    __syncthreads();
    float tot = 0.f;
#pragma unroll
    for (int i = 0; i < 8; i++) tot += red1[i];
    float mu = tot * (1.f / CS);

    float d0 = v0 - mu, d1 = v1 - mu, d2 = v2 - mu;
    float q = d0 * d0 + d1 * d1 + d2 * d2;
    for (int o = 16; o; o >>= 1) q += __shfl_xor_sync(~0u, q, o);
    if ((tid & 31) == 0) red2[tid >> 5] = q;
    __syncthreads();
    float tot2 = 0.f;
#pragma unroll
    for (int i = 0; i < 8; i++) tot2 += red2[i];
    float rsig = rsqrtf(tot2 * (1.f / CS) + 1e-5f);

    const float* e = g_emb + b * 3 * CS;
    unsigned* outp = g_bsn + (size_t)row * CS;
    outp[tid]       = f2tf(d0 * rsig * (1.f + e[CS + tid])       + e[tid]);
    outp[tid + 256] = f2tf(d1 * rsig * (1.f + e[CS + tid + 256]) + e[tid + 256]);
    outp[tid + 512] = f2tf(d2 * rsig * (1.f + e[CS + tid + 512]) + e[tid + 512]);
}

// ============================================================
// 3. QKV GEMM, cp.async double-buffered, fused RMS + q-scale
// ============================================================
__global__ __launch_bounds__(256) void qkv_mma2(const float* __restrict__ rqw,
                                                const float* __restrict__ rkw) {
    __shared__ unsigned As[2][128][20];
    __shared__ unsigned Bs[2][16][136];
    int tid = threadIdx.x, w = tid >> 5, lane = tid & 31, g = lane >> 2, c = lane & 3;
    int wm = w & 3, wn = w >> 2;
    int n0 = blockIdx.x * 128;
    int sel = n0 / CS, nc = n0 - sel * CS;
    const unsigned* W = g_w[sel];
    int m0 = blockIdx.y * 128;

    float acc0[8][4] = {}, acc1[8][4] = {};
#pragma unroll
    for (int i = 0; i < 2; i++) {
        int ch = tid * 2 + i;
        int ar = ch >> 2, ac = (ch & 3) * 4;
        cpa16(&As[0][ar][ac], g_bsn + (size_t)(m0 + ar) * CS + ac);
        int br = ch >> 5, bc = (ch & 31) * 4;
        cpa16(&Bs[0][br][bc], W + (size_t)br * CS + nc + bc);
    }
    cp_commit(); cp_wait0();
    __syncthreads();

    int buf = 0;
    for (int it = 0; it < 48; it++) {
        if (it < 47) {
            int kn = (it + 1) * 16;
#pragma unroll
            for (int i = 0; i < 2; i++) {
                int ch = tid * 2 + i;
                int ar = ch >> 2, ac = (ch & 3) * 4;
                cpa16(&As[buf ^ 1][ar][ac], g_bsn + (size_t)(m0 + ar) * CS + kn + ac);
                int br = ch >> 5, bc = (ch & 31) * 4;
                cpa16(&Bs[buf ^ 1][br][bc], W + (size_t)(kn + br) * CS + nc + bc);
            }
            cp_commit();
        }
#pragma unroll
        for (int ks = 0; ks < 2; ks++) {
            int r0 = wm * 32 + g;
            unsigned a0[4] = {As[buf][r0][8 * ks + c], As[buf][r0 + 8][8 * ks + c],
                              As[buf][r0][8 * ks + c + 4], As[buf][r0 + 8][8 * ks + c + 4]};
            unsigned a1[4] = {As[buf][r0 + 16][8 * ks + c], As[buf][r0 + 24][8 * ks + c],
                              As[buf][r0 + 16][8 * ks + c + 4], As[buf][r0 + 24][8 * ks + c + 4]};
#pragma unroll
            for (int nt = 0; nt < 8; nt++) {
                unsigned b0 = Bs[buf][8 * ks + c][wn * 64 + 8 * nt + g];
                unsigned b1 = Bs[buf][8 * ks + c + 4][wn * 64 + 8 * nt + g];
                mma8(acc0[nt], a0, b0, b1);
                mma8(acc1[nt], a1, b0, b1);
            }
        }
        if (it < 47) {
            cp_wait0();
            __syncthreads();
            buf ^= 1;
        }
    }

    const float SC = 0.17677669529663687f;
    int bi = m0 >> 10;
    int r0g = m0 + wm * 32 + g;
#pragma unroll
    for (int mi = 0; mi < 2; mi++) {
        float (*ac)[4] = mi ? acc1 : acc0;
        int rb = r0g + mi * 16;
        int s0 = rb & 1023, s1 = s0 + 8;
#pragma unroll
        for (int hf = 0; hf < 2; hf++) {
            int h = (nc + wn * 64 + hf * 32) >> 5;
            float ss0 = 0.f, ss1 = 0.f;
#pragma unroll
            for (int nt = hf * 4; nt < hf * 4 + 4; nt++) {
                ss0 += ac[nt][0] * ac[nt][0] + ac[nt][1] * ac[nt][1];
                ss1 += ac[nt][2] * ac[nt][2] + ac[nt][3] * ac[nt][3];
            }
            float rs0 = 1.f, rs1 = 1.f;
            if (sel < 2) {
                ss0 += __shfl_xor_sync(~0u, ss0, 1); ss0 += __shfl_xor_sync(~0u, ss0, 2);
                ss1 += __shfl_xor_sync(~0u, ss1, 1); ss1 += __shfl_xor_sync(~0u, ss1, 2);
                rs0 = rsqrtf(ss0 * (1.f / 32) + 1e-5f);
                rs1 = rsqrtf(ss1 * (1.f / 32) + 1e-5f);
                if (sel == 0) { rs0 *= SC; rs1 *= SC; }
            }
            unsigned* basep = g_qkv + ((size_t)(sel * NB + bi) * NH + h) * SS * DD;
            const float* wr = (sel == 0) ? rqw : rkw;
#pragma unroll
            for (int nt = hf * 4; nt < hf * 4 + 4; nt++) {
                int d = (8 * nt + 2 * c) & 31;
                float w0 = 1.f, w1 = 1.f;
                if (sel < 2) { w0 = wr[d]; w1 = wr[d + 1]; }
                unsigned* p0 = basep + (size_t)s0 * DD + d;
                p0[0] = f2tf(ac[nt][0] * rs0 * w0); p0[1] = f2tf(ac[nt][1] * rs0 * w1);
                unsigned* p1 = basep + (size_t)s1 * DD + d;
                p1[0] = f2tf(ac[nt][2] * rs1 * w0); p1[1] = f2tf(ac[nt][3] * rs1 * w1);
            }
        }
    }
}

// ============================================================
// 4. bias via tf32 mma, beta folded, coalesced (b,h,i,j) output
// ============================================================
struct BiasSmem {
    unsigned Zs[128][132];
    unsigned WT[24][132];        // WT for mma; reused as float Out[24][132] in epilogue
    float muS[128], rsS[128];
    float AhS[24], BhS[24];
    int mS[128];
};

__global__ __launch_bounds__(256) void bias_mma2(const float* __restrict__ z,
                                                 const int* __restrict__ zmask,
                                                 const float* __restrict__ beta) {
    extern __shared__ char smem_raw[];
    BiasSmem* sm = (BiasSmem*)smem_raw;
    int i = blockIdx.y, jt = blockIdx.x * 128;
    int tid = threadIdx.x, w = tid >> 5, lane = tid & 31, g = lane >> 2, c = lane & 3;

    for (int idx = tid; idx < NH * CZ; idx += 256) {
        int n = idx >> 7, k = idx & 127;
        sm->WT[n][k] = g_wtp[idx];
    }
    if (tid < NH) { sm->AhS[tid] = g_ah[tid]; sm->BhS[tid] = g_bh[tid]; }
    if (tid < 128) sm->mS[tid] = zmask[(size_t)i * SS + jt + tid];
    __syncthreads();

    // z staging (raw fp32 bits) + LN stats; half-row per thread
    {
        int r = tid >> 1, hh = tid & 1;
        bool live = sm->mS[r] != 0;
        const float4* zr = (const float4*)(z + ((size_t)i * SS + jt + r) * CZ + hh * 64);
        float s = 0.f, q = 0.f;
#pragma unroll
        for (int t = 0; t < 16; t++) {
            float4 v = live ? zr[t] : make_float4(0.f, 0.f, 0.f, 0.f);
            s += v.x + v.y + v.z + v.w;
            q += v.x * v.x + v.y * v.y + v.z * v.z + v.w * v.w;
            *(float4*)&sm->Zs[r][hh * 64 + t * 4] = v;
        }
        s += __shfl_xor_sync(~0u, s, 1);
        q += __shfl_xor_sync(~0u, q, 1);
        if (hh == 0) {
            float mu = s * (1.f / CZ);
            float var = q * (1.f / CZ) - mu * mu;
            sm->muS[r] = mu;
            sm->rsS[r] = rsqrtf(var + 1e-5f);
        }
    }
    __syncthreads();

    float acc[3][4] = {};
#pragma unroll
    for (int ks = 0; ks < 16; ks++) {
        unsigned a[4] = {sm->Zs[16 * w + g][8 * ks + c], sm->Zs[16 * w + g + 8][8 * ks + c],
                         sm->Zs[16 * w + g][8 * ks + c + 4], sm->Zs[16 * w + g + 8][8 * ks + c + 4]};
#pragma unroll
        for (int nt = 0; nt < 3; nt++)
            mma8(acc[nt], a, sm->WT[8 * nt + g][8 * ks + c], sm->WT[8 * nt + g][8 * ks + c + 4]);
    }

    int j0 = 16 * w + g, j1 = j0 + 8;
    float mu0 = sm->muS[j0], rg0 = sm->rsS[j0], mu1 = sm->muS[j1], rg1 = sm->rsS[j1];
    bool k0m = sm->mS[j0] != 0, k1m = sm->mS[j1] != 0;

    __syncthreads();                       // all mma WT reads done; reuse as Out
    float* Ot = (float*)&sm->WT[0][0];     // [24][132]
#pragma unroll
    for (int nt = 0; nt < 3; nt++) {
        int h = 8 * nt + 2 * c;
        float A0 = sm->AhS[h], B0 = sm->BhS[h], A1 = sm->AhS[h + 1], B1 = sm->BhS[h + 1];
        Ot[h * 132 + j0]       = k0m ? rg0 * (acc[nt][0] - mu0 * A0) + B0 : -1e9f;
        Ot[(h + 1) * 132 + j0] = k0m ? rg0 * (acc[nt][1] - mu0 * A1) + B1 : -1e9f;
        Ot[h * 132 + j1]       = k1m ? rg1 * (acc[nt][2] - mu1 * A0) + B0 : -1e9f;
        Ot[(h + 1) * 132 + j1] = k1m ? rg1 * (acc[nt][3] - mu1 * A1) + B1 : -1e9f;
    }
    __syncthreads();

    // coalesced write: (b,h,i,j) with beta folded
#pragma unroll
    for (int b2 = 0; b2 < NB; b2++) {
        const float* betap = beta + ((size_t)b2 * SS + i) * SS + jt;
        for (int idx = tid; idx < 24 * 32; idx += 256) {
            int hh = idx >> 5, j4 = (idx & 31) * 4;
            float4 v = *(float4*)&Ot[hh * 132 + j4];
            float4 bt = *(const float4*)(betap + j4);
            v.x += bt.x; v.y += bt.y; v.z += bt.z; v.w += bt.w;
            *(float4*)(g_bias + ((size_t)(b2 * NH + hh) * SS + i) * SS + jt + j4) = v;
        }
    }
}

// ============================================================
// 5. flash attention: q-tile 64, 128 thr, 4 CTA/SM,
//    direct-LDG bias (beta folded), cp.async K/V double buffer
// ============================================================
struct AttnSmem {
    unsigned Ks[2][64][36];
    unsigned Vs[2][64][40];
    float    Ps[64][68];    // Q staging, then P
};

__global__ __launch_bounds__(128, 4) void attn_mma() {
    extern __shared__ char smem_raw[];
    AttnSmem* sm = (AttnSmem*)smem_raw;
    int b = blockIdx.z, h = blockIdx.y, q0 = blockIdx.x * 64;
    int tid = threadIdx.x, w = tid >> 5, lane = tid & 31, g = lane >> 2, c = lane & 3;

    const unsigned* qptr = g_qkv + ((size_t)(0 * NB + b) * NH + h) * SS * DD;
    const unsigned* kptr = g_qkv + ((size_t)(1 * NB + b) * NH + h) * SS * DD;
    const unsigned* vptr = g_qkv + ((size_t)(2 * NB + b) * NH + h) * SS * DD;
    const float* bp = g_bias + (((size_t)(b * NH + h)) * SS + q0) * SS;

    // stage Q (64x32) into Ps region + K/V tile 0
#pragma unroll
    for (int i = 0; i < 4; i++) {
        int ch = tid + 128 * i;
        int r = ch >> 3, col = (ch & 7) * 4;
        cpa16(&sm->Ps[r][col], qptr + (size_t)(q0 + r) * DD + col);
    }
#pragma unroll
    for (int i = 0; i < 4; i++) {
        int ch = tid + 128 * i;
        int r = ch >> 3, col = (ch & 7) * 4;
        cpa16(&sm->Ks[0][r][col], kptr + (size_t)r * DD + col);
        cpa16(&sm->Vs[0][r][col], vptr + (size_t)r * DD + col);
    }
    cp_commit(); cp_wait0();
    __syncthreads();

    unsigned qa[4][4];
#pragma unroll
    for (int ks = 0; ks < 4; ks++) {
        qa[ks][0] = __float_as_uint(sm->Ps[16 * w + g][8 * ks + c]);
        qa[ks][1] = __float_as_uint(sm->Ps[16 * w + g + 8][8 * ks + c]);
        qa[ks][2] = __float_as_uint(sm->Ps[16 * w + g][8 * ks + c + 4]);
        qa[ks][3] = __float_as_uint(sm->Ps[16 * w + g + 8][8 * ks + c + 4]);
    }
    // Ps rows [16w+g, 16w+g+8] are read and later written ONLY by warp w: no barrier needed

    float mr0 = -1e30f, mr1 = -1e30f, l0 = 0.f, l1 = 0.f;
    float o[4][4] = {};

    int buf = 0;
    for (int kt = 0; kt < 16; kt++) {
        int k0 = kt * 64;
        if (kt < 15) {
            int kn = k0 + 64;
#pragma unroll
            for (int i = 0; i < 4; i++) {
                int ch = tid + 128 * i;
                int r = ch >> 3, col = (ch & 7) * 4;
                cpa16(&sm->Ks[buf ^ 1][r][col], kptr + (size_t)(kn + r) * DD + col);
                cpa16(&sm->Vs[buf ^ 1][r][col], vptr + (size_t)(kn + r) * DD + col);
            }
            cp_commit();
        }

        float s[8][4] = {};
#pragma unroll
        for (int ks = 0; ks < 4; ks++) {
#pragma unroll
            for (int nt = 0; nt < 8; nt++)
                mma8(s[nt], qa[ks], sm->Ks[buf][8 * nt + g][8 * ks + c],
                                    sm->Ks[buf][8 * nt + g][8 * ks + c + 4]);
        }
        // direct bias add (beta already folded) + row max
        const float* bq0 = bp + (size_t)(16 * w + g) * SS + k0 + 2 * c;
        const float* bq1 = bq0 + 8 * SS;
        float mx0 = -1e30f, mx1 = -1e30f;
#pragma unroll
        for (int nt = 0; nt < 8; nt++) {
            float2 z0 = *(const float2*)(bq0 + 8 * nt);
            float2 z1 = *(const float2*)(bq1 + 8 * nt);
            s[nt][0] += z0.x; s[nt][1] += z0.y;
            s[nt][2] += z1.x; s[nt][3] += z1.y;
            mx0 = fmaxf(mx0, fmaxf(s[nt][0], s[nt][1]));
            mx1 = fmaxf(mx1, fmaxf(s[nt][2], s[nt][3]));
        }
        mx0 = fmaxf(mx0, __shfl_xor_sync(~0u, mx0, 1));
        mx0 = fmaxf(mx0, __shfl_xor_sync(~0u, mx0, 2));
        mx1 = fmaxf(mx1, __shfl_xor_sync(~0u, mx1, 1));
        mx1 = fmaxf(mx1, __shfl_xor_sync(~0u, mx1, 2));
        float mn0 = fmaxf(mr0, mx0), mn1 = fmaxf(mr1, mx1);
        float a0 = fexp2(fmaxf((mr0 - mn0) * L2E, -126.f));
        float a1 = fexp2(fmaxf((mr1 - mn1) * L2E, -126.f));
        float m20 = mn0 * L2E, m21 = mn1 * L2E;
        float rs0 = 0.f, rs1 = 0.f;
#pragma unroll
        for (int nt = 0; nt < 8; nt++) {
            float e0 = fexp2(fmaxf(fmaf(s[nt][0], L2E, -m20), -126.f));
            float e1 = fexp2(fmaxf(fmaf(s[nt][1], L2E, -m20), -126.f));
            float e2 = fexp2(fmaxf(fmaf(s[nt][2], L2E, -m21), -126.f));
            float e3 = fexp2(fmaxf(fmaf(s[nt][3], L2E, -m21), -126.f));
            rs0 += e0 + e1; rs1 += e2 + e3;
            float2 f0 = {e0, e1};
            *(float2*)&sm->Ps[16 * w + g][8 * nt + 2 * c] = f0;
            float2 f1 = {e2, e3};
            *(float2*)&sm->Ps[16 * w + g + 8][8 * nt + 2 * c] = f1;
        }
        rs0 += __shfl_xor_sync(~0u, rs0, 1); rs0 += __shfl_xor_sync(~0u, rs0, 2);
        rs1 += __shfl_xor_sync(~0u, rs1, 1); rs1 += __shfl_xor_sync(~0u, rs1, 2);
        l0 = l0 * a0 + rs0; l1 = l1 * a1 + rs1;
        mr0 = mn0; mr1 = mn1;
#pragma unroll
        for (int nt = 0; nt < 4; nt++) {
            o[nt][0] *= a0; o[nt][1] *= a0; o[nt][2] *= a1; o[nt][3] *= a1;
        }
        __syncwarp();
#pragma unroll
        for (int ks = 0; ks < 8; ks++) {
            unsigned pa[4] = {__float_as_uint(sm->Ps[16 * w + g][8 * ks + c]),
                              __float_as_uint(sm->Ps[16 * w + g + 8][8 * ks + c]),
                              __float_as_uint(sm->Ps[16 * w + g][8 * ks + c + 4]),
                              __float_as_uint(sm->Ps[16 * w + g + 8][8 * ks + c + 4])};
#pragma unroll
            for (int nt = 0; nt < 4; nt++)
                mma8(o[nt], pa, sm->Vs[buf][8 * ks + c][8 * nt + g],
                                sm->Vs[buf][8 * ks + c + 4][8 * nt + g]);
        }
        if (kt < 15) cp_wait0();
        __syncthreads();
        buf ^= 1;
    }
    float inv0 = 1.f / l0, inv1 = 1.f / l1;
    int r0 = q0 + 16 * w + g, r1 = r0 + 8;
#pragma unroll
    for (int nt = 0; nt < 4; nt++) {
        int col = h * DD + 8 * nt + 2 * c;
        uint2 v0 = {f2tf(o[nt][0] * inv0), f2tf(o[nt][1] * inv0)};
        *(uint2*)(g_att + ((size_t)(b * SS + r0)) * CS + col) = v0;
        uint2 v1 = {f2tf(o[nt][2] * inv1), f2tf(o[nt][3] * inv1)};
        *(uint2*)(g_att + ((size_t)(b * SS + r1)) * CS + col) = v1;
    }
}

// ============================================================
// 6. out proj: cp.async double-buffered
// ============================================================
__global__ __launch_bounds__(256) void proj_mma2(const float* __restrict__ b_o,
                                                 float* __restrict__ out) {
    __shared__ unsigned As[2][128][20];
    __shared__ unsigned Bs[2][16][136];
    int tid = threadIdx.x, w = tid >> 5, lane = tid & 31, g = lane >> 2, c = lane & 3;
    int wm = w & 3, wn = w >> 2;
    int n0 = blockIdx.x * 128, m0 = blockIdx.y * 128;
    const unsigned* W = g_w[3];

    float acc0[8][4] = {}, acc1[8][4] = {};
#pragma unroll
    for (int i = 0; i < 2; i++) {
        int ch = tid * 2 + i;
        int ar = ch >> 2, ac = (ch & 3) * 4;
        cpa16(&As[0][ar][ac], g_att + (size_t)(m0 + ar) * CS + ac);
        int br = ch >> 5, bc = (ch & 31) * 4;
        cpa16(&Bs[0][br][bc], W + (size_t)br * CS + n0 + bc);
    }
    cp_commit(); cp_wait0();
    __syncthreads();

    int buf = 0;
    for (int it = 0; it < 48; it++) {
        if (it < 47) {
            int kn = (it + 1) * 16;
#pragma unroll
            for (int i = 0; i < 2; i++) {
                int ch = tid * 2 + i;
                int ar = ch >> 2, ac = (ch & 3) * 4;
                cpa16(&As[buf ^ 1][ar][ac], g_att + (size_t)(m0 + ar) * CS + kn + ac);
                int br = ch >> 5, bc = (ch & 31) * 4;
                cpa16(&Bs[buf ^ 1][br][bc], W + (size_t)(kn + br) * CS + n0 + bc);
            }
            cp_commit();
        }
#pragma unroll
        for (int ks = 0; ks < 2; ks++) {
            int r0 = wm * 32 + g;
            unsigned a0[4] = {As[buf][r0][8 * ks + c], As[buf][r0 + 8][8 * ks + c],
                              As[buf][r0][8 * ks + c + 4], As[buf][r0 + 8][8 * ks + c + 4]};
            unsigned a1[4] = {As[buf][r0 + 16][8 * ks + c], As[buf][r0 + 24][8 * ks + c],
                              As[buf][r0 + 16][8 * ks + c + 4], As[buf][r0 + 24][8 * ks + c + 4]};
#pragma unroll
            for (int nt = 0; nt < 8; nt++) {
                unsigned b0 = Bs[buf][8 * ks + c][wn * 64 + 8 * nt + g];
                unsigned b1 = Bs[buf][8 * ks + c + 4][wn * 64 + 8 * nt + g];
                mma8(acc0[nt], a0, b0, b1);
                mma8(acc1[nt], a1, b0, b1);
            }
        }
        if (it < 47) {
            cp_wait0();
            __syncthreads();
            buf ^= 1;
        }
    }

    int bi = m0 >> 10;
    const float* gate = g_emb + bi * 3 * CS + 2 * CS;
    int r0g = m0 + wm * 32 + g;
#pragma unroll
    for (int mi = 0; mi < 2; mi++) {
        float (*ac)[4] = mi ? acc1 : acc0;
        int rb = r0g + mi * 16;
#pragma unroll
        for (int nt = 0; nt < 8; nt++) {
            int col = n0 + wn * 64 + 8 * nt + 2 * c;
            float g0 = gate[col], g1 = gate[col + 1];
            float bo0 = b_o[col], bo1 = b_o[col + 1];
            float2 v0 = {(ac[nt][0] + bo0) * g0, (ac[nt][1] + bo1) * g1};
            *(float2*)(out + (size_t)rb * CS + col) = v0;
            float2 v1 = {(ac[nt][2] + bo0) * g0, (ac[nt][3] + bo1) * g1};
            *(float2*)(out + (size_t)(rb + 8) * CS + col) = v1;
        }
    }
}

// ============================================================
extern "C" void kernel_launch(void* const* d_in, const int* in_sizes, int n_in,
                              void* d_out, int out_size) {
    const float* bs      = (const float*)d_in[0];
    const float* z       = (const float*)d_in[1];
    const float* t       = (const float*)d_in[2];
    const float* beta    = (const float*)d_in[3];
    const int*   z_mask  = (const int*)  d_in[4];
    const float* w_adaln = (const float*)d_in[5];
    const float* b_adaln = (const float*)d_in[6];
    const float* ln_z_w  = (const float*)d_in[7];
    const float* ln_z_b  = (const float*)d_in[8];
    const float* w_q     = (const float*)d_in[9];
    const float* w_k     = (const float*)d_in[10];
    const float* w_v     = (const float*)d_in[11];
    const float* w_z     = (const float*)d_in[12];
    const float* rms_q_w = (const float*)d_in[13];
    const float* rms_k_w = (const float*)d_in[14];
    const float* w_o     = (const float*)d_in[15];
    const float* b_o     = (const float*)d_in[16];
    float* out = (float*)d_out;

    static const int ATTN_SMEM = (int)sizeof(AttnSmem);
    static const int BIAS_SMEM = (int)sizeof(BiasSmem);
    cudaFuncSetAttribute(attn_mma, cudaFuncAttributeMaxDynamicSharedMemorySize, ATTN_SMEM);
    cudaFuncSetAttribute(bias_mma2, cudaFuncAttributeMaxDynamicSharedMemorySize, BIAS_SMEM);

    adaln_kernel<<<dim3(9, 2), 256>>>(t, w_adaln, b_adaln);
    wconv_kernel<<<576, 256>>>(w_q, w_k, w_v, w_o);
    bprep_kernel<<<1, 256>>>(ln_z_w, ln_z_b, w_z);
    bsnorm_kernel<<<NB * SS, 256>>>(bs);
    bias_mma2<<<dim3(8, SS), 256, BIAS_SMEM>>>(z, z_mask, beta);
    qkv_mma2<<<dim3(18, 16), 256>>>(rms_q_w, rms_k_w);
    attn_mma<<<dim3(16, NH, NB), 128, ATTN_SMEM>>>();
    proj_mma2<<<dim3(6, 16), 256>>>(b_o, out);
}